// round 9
// baseline (speedup 1.0000x reference)
#include <cuda_runtime.h>
#include <cuda_bf16.h>
#include <cstdint>
#include <math.h>

// Problem constants
#define NB   64
#define CC   512
#define CI_  256
#define HH   12
#define WW   4
#define HW   48
#define PP   (NB*HW)     // 3072
#define NM   12
#define NCF  (NB*NM)     // 768
#define EPS_ 1e-5f
#define W1SZ (CI_*CC)    // 131072
#define W2SZ (CC*CC)     // 262144

// ---------------- scratch (device globals) ------------------------------------
__device__ float          g_xt  [PP * CC];
__device__ __nv_bfloat16  g_xth [PP * CC];
__device__ __nv_bfloat16  g_xtl [PP * CC];
__device__ __nv_bfloat16  g_wh  [2 * W1SZ + 2 * W2SZ];
__device__ __nv_bfloat16  g_wl  [2 * W1SZ + 2 * W2SZ];
__device__ __nv_bfloat16  g_thh [PP * CI_];
__device__ __nv_bfloat16  g_thl [PP * CI_];
__device__ float          g_phi [PP * CI_];
__device__ __nv_bfloat16  g_pph [NCF * CI_];
__device__ __nv_bfloat16  g_ppl [NCF * CI_];
__device__ float          g_F   [PP * NCF];
__device__ float          g_M   [PP];
__device__ float          g_xln [PP * CC];
__device__ __nv_bfloat16  g_xlnh[PP * CC];
__device__ __nv_bfloat16  g_xlnl[PP * CC];
__device__ __nv_bfloat16  g_y1h [PP * CC];
__device__ __nv_bfloat16  g_y1l [PP * CC];
__device__ float          g_r2  [PP * CC];

// ---------------- primitives ---------------------------------------------------
__device__ __forceinline__ uint32_t smem_u32(const void* p) {
    uint32_t a;
    asm("{ .reg .u64 t; cvta.to.shared.u64 t, %1; cvt.u32.u64 %0, t; }"
        : "=r"(a) : "l"(p));
    return a;
}
__device__ __forceinline__ void ldsm4(uint32_t* r, uint32_t addr) {
    asm volatile("ldmatrix.sync.aligned.m8n8.x4.shared.b16 {%0,%1,%2,%3}, [%4];"
                 : "=r"(r[0]), "=r"(r[1]), "=r"(r[2]), "=r"(r[3]) : "r"(addr));
}
__device__ __forceinline__ void mma_bf16(float* d, const uint32_t* a, const uint32_t* b) {
    asm volatile("mma.sync.aligned.m16n8k16.row.col.f32.bf16.bf16.f32 "
                 "{%0,%1,%2,%3}, {%4,%5,%6,%7}, {%8,%9}, {%0,%1,%2,%3};"
                 : "+f"(d[0]), "+f"(d[1]), "+f"(d[2]), "+f"(d[3])
                 : "r"(a[0]), "r"(a[1]), "r"(a[2]), "r"(a[3]), "r"(b[0]), "r"(b[1]));
}
__device__ __forceinline__ void cp16(uint32_t s, const void* g) {
    asm volatile("cp.async.cg.shared.global [%0], [%1], 16;" :: "r"(s), "l"(g) : "memory");
}
__device__ __forceinline__ void cp_commit() {
    asm volatile("cp.async.commit_group;" ::: "memory");
}
template<int N> __device__ __forceinline__ void cp_wait() {
    asm volatile("cp.async.wait_group %0;" :: "n"(N) : "memory");
}

// 4-stage pipeline, BK=32. Stage = A(128x32 hi+lo, 16KB) + B(64x32 hi+lo, 8KB).
#define STG_BYTES   24576
#define DSMEM_BYTES 98304   // 4 stages

// packed swizzled address: 2 rows per 128B line, 8x8 XOR swizzle on 16B groups
__device__ __forceinline__ uint32_t sw_addr(int r, int sub) {
    int line = r >> 1;
    int s = ((r & 1) << 2) | sub;     // 0..7 within line
    return (uint32_t)(line * 128 + ((s ^ (line & 7)) << 4));
}

// ---------------- tensor-core GEMM, 4-stage cp.async pipeline -----------------
// C[m,n] = A[m,:]·B[n,:] with A ~ Ah+Al, B ~ Bh+Bl (3-term bf16 split).
// Tile 128x64, BK=32, 256 threads (8 warps, 4x2 warp grid, 32x32 per warp).
template<bool BIAS, bool RELU, bool ADD, bool EMITF, bool EMITS>
__device__ __forceinline__ void tgemm_body(
    const __nv_bfloat16* __restrict__ Ah, const __nv_bfloat16* __restrict__ Al,
    const __nv_bfloat16* __restrict__ Bh, const __nv_bfloat16* __restrict__ Bl,
    const float* __restrict__ bias, const float* __restrict__ addsrc,
    float* __restrict__ outf,
    __nv_bfloat16* __restrict__ oh, __nv_bfloat16* __restrict__ ol,
    int Nc, int K, int m0, int n0, uint8_t* dsm)
{
    const int tid  = threadIdx.x;
    const int lane = tid & 31, wid = tid >> 5;
    const int wm = wid & 3, wn = wid >> 2;
    const uint32_t sbase = smem_u32(dsm);

    const int rA  = (lane & 7) + ((lane >> 3) & 1) * 8;
    const int kgA = (lane >> 4) & 1;
    const int rB  = (lane & 7) + ((lane >> 4) & 1) * 8;
    const int kgB = (lane >> 3) & 1;

    float acc[2][4][4];
    #pragma unroll
    for (int mf = 0; mf < 2; mf++)
        #pragma unroll
        for (int nf = 0; nf < 4; nf++)
            #pragma unroll
            for (int q = 0; q < 4; q++) acc[mf][nf][q] = 0.f;

    const int nch = K >> 5;   // 32-K chunks (8 or 16)

    // stage one 32-K chunk into pipeline slot
    auto stage = [&](int ch, int slot) {
        const int k0 = ch << 5;
        const uint32_t abase = sbase + slot * STG_BYTES;
        const uint32_t bbase = abase + 16384;
        #pragma unroll
        for (int i = 0; i < 4; i++) {           // A: 1024 cp16
            int t = tid + i * 256;
            int h = t >> 9, rem = t & 511;
            int r = rem >> 2, g = rem & 3;
            const __nv_bfloat16* src = (h ? Al : Ah) + (size_t)(m0 + r) * K + k0 + g * 8;
            cp16(abase + h * 8192 + sw_addr(r, g), src);
        }
        #pragma unroll
        for (int i = 0; i < 2; i++) {           // B: 512 cp16
            int t = tid + i * 256;
            int h = t >> 8, rem = t & 255;
            int r = rem >> 2, g = rem & 3;
            const __nv_bfloat16* src = (h ? Bl : Bh) + (size_t)(n0 + r) * K + k0 + g * 8;
            cp16(bbase + h * 4096 + sw_addr(r, g), src);
        }
        cp_commit();
    };

    // prologue: fill 3 stages (nch >= 8 always)
    stage(0, 0); stage(1, 1); stage(2, 2);

    for (int ch = 0; ch < nch; ch++) {
        cp_wait<2>();          // stage ch landed (one group per iter, 3 in prologue)
        __syncthreads();
        const int slot = ch & 3;
        const uint32_t sAu = sbase + slot * STG_BYTES;
        const uint32_t sBu = sAu + 16384;
        #pragma unroll
        for (int ks = 0; ks < 2; ks++) {
            uint32_t a[2][2][4], b[2][2][4];
            #pragma unroll
            for (int mf = 0; mf < 2; mf++) {
                int row = wm * 32 + mf * 16 + rA;
                #pragma unroll
                for (int h = 0; h < 2; h++)
                    ldsm4(a[mf][h], sAu + h * 8192 + sw_addr(row, 2 * ks + kgA));
            }
            #pragma unroll
            for (int np = 0; np < 2; np++) {
                int row = wn * 32 + np * 16 + rB;
                #pragma unroll
                for (int h = 0; h < 2; h++)
                    ldsm4(b[np][h], sBu + h * 4096 + sw_addr(row, 2 * ks + kgB));
            }
            #pragma unroll
            for (int mf = 0; mf < 2; mf++)
                #pragma unroll
                for (int nf = 0; nf < 4; nf++) {
                    int np = nf >> 1, sub = (nf & 1) << 1;
                    mma_bf16(acc[mf][nf], a[mf][0], &b[np][0][sub]); // Ah*Bh
                    mma_bf16(acc[mf][nf], a[mf][0], &b[np][1][sub]); // Ah*Bl
                    mma_bf16(acc[mf][nf], a[mf][1], &b[np][0][sub]); // Al*Bh
                }
        }
        // keep one group per iteration so cp_wait<2> arithmetic stays exact
        if (ch + 3 < nch) stage(ch + 3, (ch + 3) & 3);
        else              cp_commit();   // empty group
    }
    // ---- epilogue ----
    const int mrow0 = m0 + wm * 32 + (lane >> 2);
    const int col0  = n0 + wn * 32 + (lane & 3) * 2;
    #pragma unroll
    for (int mf = 0; mf < 2; mf++)
        #pragma unroll
        for (int nf = 0; nf < 4; nf++)
            #pragma unroll
            for (int hf = 0; hf < 2; hf++) {
                int row = mrow0 + mf * 16 + hf * 8;
                int col = col0 + nf * 8;
                float vx = acc[mf][nf][hf * 2];
                float vy = acc[mf][nf][hf * 2 + 1];
                if (BIAS) { vx += bias[col]; vy += bias[col + 1]; }
                if (RELU) { vx = fmaxf(vx, 0.f); vy = fmaxf(vy, 0.f); }
                if (ADD) {
                    const float2 a2 = *(const float2*)&addsrc[(size_t)row * Nc + col];
                    vx += a2.x; vy += a2.y;
                }
                if (EMITF) *(float2*)&outf[(size_t)row * Nc + col] = make_float2(vx, vy);
                if (EMITS) {
                    __nv_bfloat16 hx = __float2bfloat16(vx);
                    __nv_bfloat16 hy = __float2bfloat16(vy);
                    __nv_bfloat16 lx = __float2bfloat16(vx - __bfloat162float(hx));
                    __nv_bfloat16 ly = __float2bfloat16(vy - __bfloat162float(hy));
                    *(__nv_bfloat162*)&oh[(size_t)row * Nc + col] = __nv_bfloat162(hx, hy);
                    *(__nv_bfloat162*)&ol[(size_t)row * Nc + col] = __nv_bfloat162(lx, ly);
                }
            }
}

template<bool BIAS, bool RELU, bool ADD, bool EMITF, bool EMITS>
__global__ __launch_bounds__(256) void tgemm_kernel(
    const __nv_bfloat16* __restrict__ Ah, const __nv_bfloat16* __restrict__ Al,
    const __nv_bfloat16* __restrict__ Bh, const __nv_bfloat16* __restrict__ Bl,
    const float* __restrict__ bias, const float* __restrict__ addsrc,
    float* __restrict__ outf,
    __nv_bfloat16* __restrict__ oh, __nv_bfloat16* __restrict__ ol,
    int Nc, int K)
{
    extern __shared__ uint8_t dsm[];
    tgemm_body<BIAS, RELU, ADD, EMITF, EMITS>(Ah, Al, Bh, Bl, bias, addsrc,
        outf, oh, ol, Nc, K, blockIdx.y * 128, blockIdx.x * 64, dsm);
}

// dual projection: z=0 -> theta (bf16-split out), z=1 -> phi (f32 out)
__global__ __launch_bounds__(256) void tgemm_dual_kernel(
    const __nv_bfloat16* __restrict__ Ah, const __nv_bfloat16* __restrict__ Al,
    const __nv_bfloat16* __restrict__ B0h, const __nv_bfloat16* __restrict__ B0l,
    const __nv_bfloat16* __restrict__ B1h, const __nv_bfloat16* __restrict__ B1l,
    const float* __restrict__ bias0, const float* __restrict__ bias1,
    __nv_bfloat16* __restrict__ thh, __nv_bfloat16* __restrict__ thl,
    float* __restrict__ phi, int Nc, int K)
{
    extern __shared__ uint8_t dsm[];
    if (blockIdx.z == 0)
        tgemm_body<true, false, false, false, true>(Ah, Al, B0h, B0l, bias0, nullptr,
            nullptr, thh, thl, Nc, K, blockIdx.y * 128, blockIdx.x * 64, dsm);
    else
        tgemm_body<true, false, false, true, false>(Ah, Al, B1h, B1l, bias1, nullptr,
            phi, nullptr, nullptr, Nc, K, blockIdx.y * 128, blockIdx.x * 64, dsm);
}

// ---------------- transpose + split: x[N,C,H,W] -> xt, xt_hi, xt_lo -----------
__global__ __launch_bounds__(256) void transpose_kernel(const float* __restrict__ x,
                                                        float* __restrict__ xt,
                                                        __nv_bfloat16* __restrict__ xh,
                                                        __nv_bfloat16* __restrict__ xl) {
    int j  = blockIdx.x;
    int c0 = blockIdx.y * 128;
    __shared__ float t[128][49];
    int tid = threadIdx.x;
    const float* xb = x + j * (CC * HW);
    for (int idx = tid; idx < 128 * HW; idx += 256) {
        int cc = idx / HW, s = idx % HW;
        t[cc][s] = xb[(c0 + cc) * HW + s];
    }
    __syncthreads();
    size_t ob = (size_t)j * HW * CC;
    for (int idx = tid; idx < HW * 128; idx += 256) {
        int s = idx >> 7, cc = idx & 127;
        float v = t[cc][s];
        size_t o = ob + s * CC + c0 + cc;
        xt[o] = v;
        __nv_bfloat16 h = __float2bfloat16(v);
        xh[o] = h;
        xl[o] = __float2bfloat16(v - __bfloat162float(h));
    }
}

// ---------------- all-weights fp32 -> bf16 hi/lo split (one launch) -----------
__global__ __launch_bounds__(256) void split_all_kernel(const float* __restrict__ w0,
                                                        const float* __restrict__ w1,
                                                        const float* __restrict__ w2,
                                                        const float* __restrict__ w3,
                                                        __nv_bfloat16* __restrict__ h,
                                                        __nv_bfloat16* __restrict__ l) {
    int i = blockIdx.x * 256 + threadIdx.x;   // total 2*W1SZ + 2*W2SZ
    const float* src; int off;
    if (i < W1SZ)                  { src = w0; off = i; }
    else if (i < 2 * W1SZ)         { src = w1; off = i - W1SZ; }
    else if (i < 2 * W1SZ + W2SZ)  { src = w2; off = i - 2 * W1SZ; }
    else                           { src = w3; off = i - 2 * W1SZ - W2SZ; }
    float v = src[off];
    __nv_bfloat16 a = __float2bfloat16(v);
    h[i] = a;
    l[i] = __float2bfloat16(v - __bfloat162float(a));
}

// ---------------- maxpool 2x2 on phi -> phip hi/lo (one block per (m,i)) ------
__global__ __launch_bounds__(256) void pool_kernel(const float* __restrict__ phi,
                                                   __nv_bfloat16* __restrict__ ph,
                                                   __nv_bfloat16* __restrict__ pl) {
    int m = blockIdx.x, i = blockIdx.y;
    int c = threadIdx.x;   // 256 = CI
    int phh = m >> 1, pw = m & 1;
    int s0 = (2 * phh) * WW + 2 * pw;
    const float* b = phi + (size_t)(i * HW) * CI_ + c;
    float v = b[(size_t)s0 * CI_];
    v = fmaxf(v, b[(size_t)(s0 + 1) * CI_]);
    v = fmaxf(v, b[(size_t)(s0 + WW) * CI_]);
    v = fmaxf(v, b[(size_t)(s0 + WW + 1) * CI_]);
    size_t o = (size_t)(i * NM + m) * CI_ + c;
    __nv_bfloat16 h = __float2bfloat16(v);
    ph[o] = h;
    pl[o] = __float2bfloat16(v - __bfloat162float(h));
}

// ---------------- reduce F -> M (float4-vectorized group max) -----------------
__global__ __launch_bounds__(256) void reduceM_kernel(const float* __restrict__ F,
                                                      float* __restrict__ Mv) {
    int p = blockIdx.x * 8 + (threadIdx.x >> 5);
    int lane = threadIdx.x & 31;
    const float4* row4 = (const float4*)(F + (size_t)p * NCF);  // 192 float4s
    float s = 0.f;
    #pragma unroll
    for (int g = lane; g < NB; g += 32) {
        float4 a = row4[3 * g], b = row4[3 * g + 1], c = row4[3 * g + 2];
        float v = fmaxf(fmaxf(fmaxf(a.x, a.y), fmaxf(a.z, a.w)),
                  fmaxf(fmaxf(fmaxf(b.x, b.y), fmaxf(b.z, b.w)),
                        fmaxf(fmaxf(c.x, c.y), fmaxf(c.z, c.w))));
        s += v;
    }
    #pragma unroll
    for (int o = 16; o > 0; o >>= 1) s += __shfl_down_sync(0xffffffffu, s, o);
    if (lane == 0) Mv[p] = s * (1.0f / 12.0f);
}

// ---------------- block reduction helper --------------------------------------
__device__ __forceinline__ float blockReduceSum256(float v, float* sbuf) {
    #pragma unroll
    for (int o = 16; o > 0; o >>= 1) v += __shfl_down_sync(0xffffffffu, v, o);
    int lane = threadIdx.x & 31, w = threadIdx.x >> 5;
    if (lane == 0) sbuf[w] = v;
    __syncthreads();
    v = (threadIdx.x < 8) ? sbuf[threadIdx.x] : 0.f;
    if (w == 0) {
        #pragma unroll
        for (int o = 4; o > 0; o >>= 1) v += __shfl_down_sync(0xffu, v, o);
    }
    return v;
}

// ---------------- res1 + LN1 (emits f32 + hi/lo split) ------------------------
__global__ __launch_bounds__(256) void ln1_kernel(const float* __restrict__ xt,
                                                  const float* __restrict__ Mv,
                                                  const float* __restrict__ gam,
                                                  const float* __restrict__ bet,
                                                  float* __restrict__ xln,
                                                  __nv_bfloat16* __restrict__ xh,
                                                  __nv_bfloat16* __restrict__ xl) {
    int j = blockIdx.x, tid = threadIdx.x;
    __shared__ float sbuf[32];
    __shared__ float s_mu, s_rstd;
    __shared__ float s_scale[HW];
    if (tid < HW) s_scale[tid] = 1.0f + Mv[j * HW + tid];
    __syncthreads();
    const float* base = xt + (size_t)j * (HW * CC);
    float sum = 0.f, sq = 0.f;
    for (int idx = tid; idx < HW * CC; idx += 256) {
        float v = base[idx] * s_scale[idx >> 9];
        sum += v; sq += v * v;
    }
    float ts = blockReduceSum256(sum, sbuf);
    __syncthreads();
    float tq = blockReduceSum256(sq, sbuf);
    if (tid == 0) {
        float mu = ts * (1.0f / (HW * CC));
        float var = tq * (1.0f / (HW * CC)) - mu * mu;
        s_mu = mu; s_rstd = rsqrtf(var + EPS_);
    }
    __syncthreads();
    float mu = s_mu, rstd = s_rstd;
    size_t ob = (size_t)j * (HW * CC);
    for (int idx = tid; idx < HW * CC; idx += 256) {
        int s = idx >> 9, c = idx & 511;
        float v = base[idx] * s_scale[s];
        float r = (v - mu) * rstd * gam[c * HW + s] + bet[c * HW + s];
        xln[ob + idx] = r;
        __nv_bfloat16 h = __float2bfloat16(r);
        xh[ob + idx] = h;
        xl[ob + idx] = __float2bfloat16(r - __bfloat162float(h));
    }
}

// ---------------- LN2 + output in NCHW (smem-transposed, fully coalesced) -----
__global__ __launch_bounds__(256) void ln2_kernel(const float* __restrict__ r2,
                                                  const float* __restrict__ gam,
                                                  const float* __restrict__ bet,
                                                  float* __restrict__ out) {
    int j = blockIdx.x, tid = threadIdx.x;
    __shared__ float sbuf[32];
    __shared__ float s_mu, s_rstd;
    __shared__ float t[128][49];
    const float* base = r2 + (size_t)j * (HW * CC);
    float sum = 0.f, sq = 0.f;
    for (int idx = tid; idx < HW * CC; idx += 256) {
        float v = base[idx];
        sum += v; sq += v * v;
    }
    float ts = blockReduceSum256(sum, sbuf);
    __syncthreads();
    float tq = blockReduceSum256(sq, sbuf);
    if (tid == 0) {
        float mu = ts * (1.0f / (HW * CC));
        float var = tq * (1.0f / (HW * CC)) - mu * mu;
        s_mu = mu; s_rstd = rsqrtf(var + EPS_);
    }
    __syncthreads();
    float mu = s_mu, rstd = s_rstd;
    float* o = out + (size_t)j * (HW * CC);
    for (int c0 = 0; c0 < CC; c0 += 128) {
        __syncthreads();
        for (int idx = tid; idx < HW * 128; idx += 256) {
            int sp = idx >> 7, cc = idx & 127;
            t[cc][sp] = base[sp * CC + c0 + cc];
        }
        __syncthreads();
        for (int idx = tid; idx < 128 * HW; idx += 256) {
            int cc = idx / HW, sp = idx % HW;
            int oi = (c0 + cc) * HW + sp;
            o[oi] = (t[cc][sp] - mu) * rstd * gam[oi] + bet[oi];
        }
    }
}

// ---------------- launcher ----------------------------------------------------
extern "C" void kernel_launch(void* const* d_in, const int* in_sizes, int n_in,
                              void* d_out, int out_size) {
    const float* x       = (const float*)d_in[0];
    const float* theta_w = (const float*)d_in[1];
    const float* theta_b = (const float*)d_in[2];
    const float* phi_w   = (const float*)d_in[3];
    const float* phi_b   = (const float*)d_in[4];
    const float* conv1_w = (const float*)d_in[5];
    const float* conv2_w = (const float*)d_in[6];
    const float* ln1_g   = (const float*)d_in[7];
    const float* ln1_b   = (const float*)d_in[8];
    const float* ln2_g   = (const float*)d_in[9];
    const float* ln2_b   = (const float*)d_in[10];
    float* out = (float*)d_out;

    float *xt, *phi, *F, *Mv, *xln, *r2;
    __nv_bfloat16 *xth, *xtl, *wh, *wl, *thh, *thl, *pph, *ppl, *xlnh, *xlnl, *y1h, *y1l;
    cudaGetSymbolAddress((void**)&xt,   g_xt);
    cudaGetSymbolAddress((void**)&xth,  g_xth);
    cudaGetSymbolAddress((void**)&xtl,  g_xtl);
    cudaGetSymbolAddress((void**)&wh,   g_wh);
    cudaGetSymbolAddress((void**)&wl,   g_wl);
    cudaGetSymbolAddress((void**)&thh,  g_thh);
    cudaGetSymbolAddress((void**)&thl,  g_thl);
    cudaGetSymbolAddress((void**)&phi,  g_phi);
    cudaGetSymbolAddress((void**)&pph,  g_pph);
    cudaGetSymbolAddress((void**)&ppl,  g_ppl);
    cudaGetSymbolAddress((void**)&F,    g_F);
    cudaGetSymbolAddress((void**)&Mv,   g_M);
    cudaGetSymbolAddress((void**)&xln,  g_xln);
    cudaGetSymbolAddress((void**)&xlnh, g_xlnh);
    cudaGetSymbolAddress((void**)&xlnl, g_xlnl);
    cudaGetSymbolAddress((void**)&y1h,  g_y1h);
    cudaGetSymbolAddress((void**)&y1l,  g_y1l);
    cudaGetSymbolAddress((void**)&r2,   g_r2);

    cudaFuncSetAttribute(tgemm_dual_kernel,
        cudaFuncAttributeMaxDynamicSharedMemorySize, DSMEM_BYTES);
    cudaFuncSetAttribute(tgemm_kernel<false, false, false, true, false>,
        cudaFuncAttributeMaxDynamicSharedMemorySize, DSMEM_BYTES);
    cudaFuncSetAttribute(tgemm_kernel<false, true, false, false, true>,
        cudaFuncAttributeMaxDynamicSharedMemorySize, DSMEM_BYTES);
    cudaFuncSetAttribute(tgemm_kernel<false, false, true, true, false>,
        cudaFuncAttributeMaxDynamicSharedMemorySize, DSMEM_BYTES);

    const int W1 = W1SZ, W2 = W2SZ;
    const int SPLIT_TOTAL = 2 * W1 + 2 * W2;

    transpose_kernel<<<dim3(NB, 4), 256>>>(x, xt, xth, xtl);
    split_all_kernel<<<SPLIT_TOTAL / 256, 256>>>(theta_w, phi_w, conv1_w, conv2_w, wh, wl);

    // theta (bf16-split out) & phi (f32 out): [3072,512]@[256,512]^T
    tgemm_dual_kernel<<<dim3(CI_ / 64, PP / 128, 2), 256, DSMEM_BYTES>>>(
        xth, xtl, wh, wl, wh + W1, wl + W1, theta_b, phi_b, thh, thl, phi, CI_, CC);
    pool_kernel<<<dim3(NM, NB), 256>>>(phi, pph, ppl);
    // F = theta @ phip^T : [3072,256]@[768,256]^T
    tgemm_kernel<false, false, false, true, false><<<dim3(NCF / 64, PP / 128), 256, DSMEM_BYTES>>>(
        thh, thl, pph, ppl, nullptr, nullptr, F, nullptr, nullptr, NCF, CI_);
    reduceM_kernel<<<PP / 8, 256>>>(F, Mv);
    ln1_kernel<<<NB, 256>>>(xt, Mv, ln1_g, ln1_b, xln, xlnh, xlnl);
    // y1 = relu(xln @ conv1_w^T) -> bf16 split
    tgemm_kernel<false, true, false, false, true><<<dim3(CC / 64, PP / 128), 256, DSMEM_BYTES>>>(
        xlnh, xlnl, wh + 2 * W1, wl + 2 * W1, nullptr, nullptr, nullptr, y1h, y1l, CC, CC);
    // r2 = xln + y1 @ conv2_w^T -> f32
    tgemm_kernel<false, false, true, true, false><<<dim3(CC / 64, PP / 128), 256, DSMEM_BYTES>>>(
        y1h, y1l, wh + 2 * W1 + W2, wl + 2 * W1 + W2, nullptr, xln, r2, nullptr, nullptr, CC, CC);
    ln2_kernel<<<NB, 256>>>(r2, ln2_g, ln2_b, out);
}

// round 10
// speedup vs baseline: 1.0321x; 1.0321x over previous
#include <cuda_runtime.h>
#include <cuda_bf16.h>
#include <cstdint>
#include <math.h>

// Problem constants
#define NB   64
#define CC   512
#define CI_  256
#define HH   12
#define WW   4
#define HW   48
#define PP   (NB*HW)     // 3072
#define NM   12
#define NCF  (NB*NM)     // 768
#define EPS_ 1e-5f
#define W1SZ (CI_*CC)    // 131072
#define W2SZ (CC*CC)     // 262144

// ---------------- scratch (device globals) ------------------------------------
__device__ float          g_xt  [PP * CC];
__device__ __nv_bfloat16  g_xth [PP * CC];
__device__ __nv_bfloat16  g_xtl [PP * CC];
__device__ __nv_bfloat16  g_wh  [2 * W1SZ + 2 * W2SZ];
__device__ __nv_bfloat16  g_wl  [2 * W1SZ + 2 * W2SZ];
__device__ __nv_bfloat16  g_thh [PP * CI_];
__device__ __nv_bfloat16  g_thl [PP * CI_];
__device__ float          g_phi [PP * CI_];
__device__ __nv_bfloat16  g_pph [NCF * CI_];
__device__ __nv_bfloat16  g_ppl [NCF * CI_];
__device__ float          g_F   [PP * NCF];
__device__ float          g_M   [PP];
__device__ float          g_xln [PP * CC];
__device__ __nv_bfloat16  g_xlnh[PP * CC];
__device__ __nv_bfloat16  g_xlnl[PP * CC];
__device__ __nv_bfloat16  g_y1h [PP * CC];
__device__ __nv_bfloat16  g_y1l [PP * CC];
__device__ float          g_r2  [PP * CC];

// ---------------- primitives ---------------------------------------------------
__device__ __forceinline__ uint32_t smem_u32(const void* p) {
    uint32_t a;
    asm("{ .reg .u64 t; cvta.to.shared.u64 t, %1; cvt.u32.u64 %0, t; }"
        : "=r"(a) : "l"(p));
    return a;
}
__device__ __forceinline__ void ldsm4(uint32_t* r, uint32_t addr) {
    asm volatile("ldmatrix.sync.aligned.m8n8.x4.shared.b16 {%0,%1,%2,%3}, [%4];"
                 : "=r"(r[0]), "=r"(r[1]), "=r"(r[2]), "=r"(r[3]) : "r"(addr));
}
__device__ __forceinline__ void mma_bf16(float* d, const uint32_t* a, const uint32_t* b) {
    asm volatile("mma.sync.aligned.m16n8k16.row.col.f32.bf16.bf16.f32 "
                 "{%0,%1,%2,%3}, {%4,%5,%6,%7}, {%8,%9}, {%0,%1,%2,%3};"
                 : "+f"(d[0]), "+f"(d[1]), "+f"(d[2]), "+f"(d[3])
                 : "r"(a[0]), "r"(a[1]), "r"(a[2]), "r"(a[3]), "r"(b[0]), "r"(b[1]));
}
__device__ __forceinline__ void cp16(uint32_t s, const void* g) {
    asm volatile("cp.async.cg.shared.global [%0], [%1], 16;" :: "r"(s), "l"(g) : "memory");
}
__device__ __forceinline__ void cp_commit() {
    asm volatile("cp.async.commit_group;" ::: "memory");
}
template<int N> __device__ __forceinline__ void cp_wait() {
    asm volatile("cp.async.wait_group %0;" :: "n"(N) : "memory");
}

// smem layout (dynamic, 96 KB): A buffers @ {0, 32K}, B buffers @ {64K, 80K}
#define SMA(b)  ((b) * 32768)
#define SMB(b)  (65536 + (b) * 16384)
#define DSMEM_BYTES 98304

// ---------------- tensor-core GEMM, cp.async double-buffered ------------------
// C[m,n] = A[m,:]·B[n,:] with A ~ Ah+Al, B ~ Bh+Bl (3-term bf16 split).
// Tile 128x64, BK=64, 128 threads (4 warps, 2x2 grid, 64x32 per warp).
template<bool BIAS, bool RELU, bool ADD, bool EMITF, bool EMITS>
__device__ __forceinline__ void tgemm_body(
    const __nv_bfloat16* __restrict__ Ah, const __nv_bfloat16* __restrict__ Al,
    const __nv_bfloat16* __restrict__ Bh, const __nv_bfloat16* __restrict__ Bl,
    const float* __restrict__ bias, const float* __restrict__ addsrc,
    float* __restrict__ outf,
    __nv_bfloat16* __restrict__ oh, __nv_bfloat16* __restrict__ ol,
    int Nc, int K, int m0, int n0, uint8_t* dsm)
{
    const int tid  = threadIdx.x;
    const int lane = tid & 31, wid = tid >> 5;
    const int wm = wid & 1, wn = wid >> 1;       // 2x2 warp grid
    const uint32_t sbase = smem_u32(dsm);

    const int rA  = (lane & 7) + ((lane >> 3) & 1) * 8;
    const int kgA = (lane >> 4) & 1;
    const int rB  = (lane & 7) + ((lane >> 4) & 1) * 8;
    const int kgB = (lane >> 3) & 1;
    const int l7  = lane & 7;

    float acc[4][4][4];                          // 64x32 per warp
    #pragma unroll
    for (int mf = 0; mf < 4; mf++)
        #pragma unroll
        for (int nf = 0; nf < 4; nf++)
            #pragma unroll
            for (int q = 0; q < 4; q++) acc[mf][nf][q] = 0.f;

    const int nch = K >> 6;

    auto stage = [&](int ch, int b) {
        const int k0 = ch << 6;
        #pragma unroll
        for (int h = 0; h < 2; h++) {            // A: 128 rows x 8 groups each h
            const __nv_bfloat16* src = h ? Al : Ah;
            uint32_t dst = sbase + SMA(b) + h * 16384;
            #pragma unroll
            for (int i = 0; i < 8; i++) {
                int t = tid + i * 128;           // 0..1023
                int r = t >> 3, g = t & 7;
                cp16(dst + r * 128 + ((g ^ (r & 7)) << 4),
                     src + (size_t)(m0 + r) * K + k0 + g * 8);
            }
        }
        #pragma unroll
        for (int h = 0; h < 2; h++) {            // B: 64 rows x 8 groups each h
            const __nv_bfloat16* src = h ? Bl : Bh;
            uint32_t dst = sbase + SMB(b) + h * 8192;
            #pragma unroll
            for (int i = 0; i < 4; i++) {
                int t = tid + i * 128;           // 0..511
                int r = t >> 3, g = t & 7;
                cp16(dst + r * 128 + ((g ^ (r & 7)) << 4),
                     src + (size_t)(n0 + r) * K + k0 + g * 8);
            }
        }
        cp_commit();
    };

    stage(0, 0);
    for (int ch = 0; ch < nch; ch++) {
        const int buf = ch & 1;
        if (ch + 1 < nch) { stage(ch + 1, buf ^ 1); cp_wait<1>(); }
        else              { cp_wait<0>(); }
        __syncthreads();
        const uint32_t sAu = sbase + SMA(buf);
        const uint32_t sBu = sbase + SMB(buf);
        #pragma unroll
        for (int ks = 0; ks < 4; ks++) {
            uint32_t a[4][2][4], b[2][2][4];
            const int xA = ((ks * 2 + kgA) ^ l7) << 4;
            const int xB = ((ks * 2 + kgB) ^ l7) << 4;
            #pragma unroll
            for (int mf = 0; mf < 4; mf++) {
                int row = wm * 64 + mf * 16 + rA;
                #pragma unroll
                for (int h = 0; h < 2; h++)
                    ldsm4(a[mf][h], sAu + h * 16384 + row * 128 + xA);
            }
            #pragma unroll
            for (int np = 0; np < 2; np++) {
                int row = wn * 32 + np * 16 + rB;
                #pragma unroll
                for (int h = 0; h < 2; h++)
                    ldsm4(b[np][h], sBu + h * 8192 + row * 128 + xB);
            }
            #pragma unroll
            for (int mf = 0; mf < 4; mf++)
                #pragma unroll
                for (int nf = 0; nf < 4; nf++) {
                    int np = nf >> 1, sub = (nf & 1) << 1;
                    mma_bf16(acc[mf][nf], a[mf][0], &b[np][0][sub]); // Ah*Bh
                    mma_bf16(acc[mf][nf], a[mf][0], &b[np][1][sub]); // Ah*Bl
                    mma_bf16(acc[mf][nf], a[mf][1], &b[np][0][sub]); // Al*Bh
                }
        }
        __syncthreads();
    }
    // ---- epilogue ----
    const int mrow0 = m0 + wm * 64 + (lane >> 2);
    const int col0  = n0 + wn * 32 + (lane & 3) * 2;
    #pragma unroll
    for (int mf = 0; mf < 4; mf++)
        #pragma unroll
        for (int nf = 0; nf < 4; nf++)
            #pragma unroll
            for (int hf = 0; hf < 2; hf++) {
                int row = mrow0 + mf * 16 + hf * 8;
                int col = col0 + nf * 8;
                float vx = acc[mf][nf][hf * 2];
                float vy = acc[mf][nf][hf * 2 + 1];
                if (BIAS) { vx += bias[col]; vy += bias[col + 1]; }
                if (RELU) { vx = fmaxf(vx, 0.f); vy = fmaxf(vy, 0.f); }
                if (ADD) {
                    const float2 a2 = *(const float2*)&addsrc[(size_t)row * Nc + col];
                    vx += a2.x; vy += a2.y;
                }
                if (EMITF) *(float2*)&outf[(size_t)row * Nc + col] = make_float2(vx, vy);
                if (EMITS) {
                    __nv_bfloat16 hx = __float2bfloat16(vx);
                    __nv_bfloat16 hy = __float2bfloat16(vy);
                    __nv_bfloat16 lx = __float2bfloat16(vx - __bfloat162float(hx));
                    __nv_bfloat16 ly = __float2bfloat16(vy - __bfloat162float(hy));
                    *(__nv_bfloat162*)&oh[(size_t)row * Nc + col] = __nv_bfloat162(hx, hy);
                    *(__nv_bfloat162*)&ol[(size_t)row * Nc + col] = __nv_bfloat162(lx, ly);
                }
            }
}

template<bool BIAS, bool RELU, bool ADD, bool EMITF, bool EMITS>
__global__ __launch_bounds__(128) void tgemm_kernel(
    const __nv_bfloat16* __restrict__ Ah, const __nv_bfloat16* __restrict__ Al,
    const __nv_bfloat16* __restrict__ Bh, const __nv_bfloat16* __restrict__ Bl,
    const float* __restrict__ bias, const float* __restrict__ addsrc,
    float* __restrict__ outf,
    __nv_bfloat16* __restrict__ oh, __nv_bfloat16* __restrict__ ol,
    int Nc, int K)
{
    extern __shared__ uint8_t dsm[];
    tgemm_body<BIAS, RELU, ADD, EMITF, EMITS>(Ah, Al, Bh, Bl, bias, addsrc,
        outf, oh, ol, Nc, K, blockIdx.y * 128, blockIdx.x * 64, dsm);
}

// dual projection: z=0 -> theta (bf16-split out), z=1 -> phi (f32 out)
__global__ __launch_bounds__(128) void tgemm_dual_kernel(
    const __nv_bfloat16* __restrict__ Ah, const __nv_bfloat16* __restrict__ Al,
    const __nv_bfloat16* __restrict__ B0h, const __nv_bfloat16* __restrict__ B0l,
    const __nv_bfloat16* __restrict__ B1h, const __nv_bfloat16* __restrict__ B1l,
    const float* __restrict__ bias0, const float* __restrict__ bias1,
    __nv_bfloat16* __restrict__ thh, __nv_bfloat16* __restrict__ thl,
    float* __restrict__ phi, int Nc, int K)
{
    extern __shared__ uint8_t dsm[];
    if (blockIdx.z == 0)
        tgemm_body<true, false, false, false, true>(Ah, Al, B0h, B0l, bias0, nullptr,
            nullptr, thh, thl, Nc, K, blockIdx.y * 128, blockIdx.x * 64, dsm);
    else
        tgemm_body<true, false, false, true, false>(Ah, Al, B1h, B1l, bias1, nullptr,
            phi, nullptr, nullptr, Nc, K, blockIdx.y * 128, blockIdx.x * 64, dsm);
}

// ---------------- transpose + split: x[N,C,H,W] -> xt, xt_hi, xt_lo -----------
__global__ __launch_bounds__(256) void transpose_kernel(const float* __restrict__ x,
                                                        float* __restrict__ xt,
                                                        __nv_bfloat16* __restrict__ xh,
                                                        __nv_bfloat16* __restrict__ xl) {
    int j  = blockIdx.x;
    int c0 = blockIdx.y * 128;
    __shared__ float t[128][49];
    int tid = threadIdx.x;
    const float* xb = x + j * (CC * HW);
    for (int idx = tid; idx < 128 * HW; idx += 256) {
        int cc = idx / HW, s = idx % HW;
        t[cc][s] = xb[(c0 + cc) * HW + s];
    }
    __syncthreads();
    size_t ob = (size_t)j * HW * CC;
    for (int idx = tid; idx < HW * 128; idx += 256) {
        int s = idx >> 7, cc = idx & 127;
        float v = t[cc][s];
        size_t o = ob + s * CC + c0 + cc;
        xt[o] = v;
        __nv_bfloat16 h = __float2bfloat16(v);
        xh[o] = h;
        xl[o] = __float2bfloat16(v - __bfloat162float(h));
    }
}

// ---------------- all-weights fp32 -> bf16 hi/lo split (one launch) -----------
__global__ __launch_bounds__(256) void split_all_kernel(const float* __restrict__ w0,
                                                        const float* __restrict__ w1,
                                                        const float* __restrict__ w2,
                                                        const float* __restrict__ w3,
                                                        __nv_bfloat16* __restrict__ h,
                                                        __nv_bfloat16* __restrict__ l) {
    int i = blockIdx.x * 256 + threadIdx.x;   // total 2*W1SZ + 2*W2SZ
    const float* src; int off;
    if (i < W1SZ)                  { src = w0; off = i; }
    else if (i < 2 * W1SZ)         { src = w1; off = i - W1SZ; }
    else if (i < 2 * W1SZ + W2SZ)  { src = w2; off = i - 2 * W1SZ; }
    else                           { src = w3; off = i - 2 * W1SZ - W2SZ; }
    float v = src[off];
    __nv_bfloat16 a = __float2bfloat16(v);
    h[i] = a;
    l[i] = __float2bfloat16(v - __bfloat162float(a));
}

// ---------------- maxpool 2x2 on phi -> phip hi/lo (one block per (m,i)) ------
__global__ __launch_bounds__(256) void pool_kernel(const float* __restrict__ phi,
                                                   __nv_bfloat16* __restrict__ ph,
                                                   __nv_bfloat16* __restrict__ pl) {
    int m = blockIdx.x, i = blockIdx.y;
    int c = threadIdx.x;   // 256 = CI
    int phh = m >> 1, pw = m & 1;
    int s0 = (2 * phh) * WW + 2 * pw;
    const float* b = phi + (size_t)(i * HW) * CI_ + c;
    float v = b[(size_t)s0 * CI_];
    v = fmaxf(v, b[(size_t)(s0 + 1) * CI_]);
    v = fmaxf(v, b[(size_t)(s0 + WW) * CI_]);
    v = fmaxf(v, b[(size_t)(s0 + WW + 1) * CI_]);
    size_t o = (size_t)(i * NM + m) * CI_ + c;
    __nv_bfloat16 h = __float2bfloat16(v);
    ph[o] = h;
    pl[o] = __float2bfloat16(v - __bfloat162float(h));
}

// ---------------- reduce F -> M (float4-vectorized group max) -----------------
__global__ __launch_bounds__(256) void reduceM_kernel(const float* __restrict__ F,
                                                      float* __restrict__ Mv) {
    int p = blockIdx.x * 8 + (threadIdx.x >> 5);
    int lane = threadIdx.x & 31;
    const float4* row4 = (const float4*)(F + (size_t)p * NCF);  // 192 float4s
    float s = 0.f;
    #pragma unroll
    for (int g = lane; g < NB; g += 32) {
        float4 a = row4[3 * g], b = row4[3 * g + 1], c = row4[3 * g + 2];
        float v = fmaxf(fmaxf(fmaxf(a.x, a.y), fmaxf(a.z, a.w)),
                  fmaxf(fmaxf(fmaxf(b.x, b.y), fmaxf(b.z, b.w)),
                        fmaxf(fmaxf(c.x, c.y), fmaxf(c.z, c.w))));
        s += v;
    }
    #pragma unroll
    for (int o = 16; o > 0; o >>= 1) s += __shfl_down_sync(0xffffffffu, s, o);
    if (lane == 0) Mv[p] = s * (1.0f / 12.0f);
}

// ---------------- block reduction helper --------------------------------------
__device__ __forceinline__ float blockReduceSum256(float v, float* sbuf) {
    #pragma unroll
    for (int o = 16; o > 0; o >>= 1) v += __shfl_down_sync(0xffffffffu, v, o);
    int lane = threadIdx.x & 31, w = threadIdx.x >> 5;
    if (lane == 0) sbuf[w] = v;
    __syncthreads();
    v = (threadIdx.x < 8) ? sbuf[threadIdx.x] : 0.f;
    if (w == 0) {
        #pragma unroll
        for (int o = 4; o > 0; o >>= 1) v += __shfl_down_sync(0xffu, v, o);
    }
    return v;
}

// ---------------- res1 + LN1 (emits f32 + hi/lo split) ------------------------
__global__ __launch_bounds__(256) void ln1_kernel(const float* __restrict__ xt,
                                                  const float* __restrict__ Mv,
                                                  const float* __restrict__ gam,
                                                  const float* __restrict__ bet,
                                                  float* __restrict__ xln,
                                                  __nv_bfloat16* __restrict__ xh,
                                                  __nv_bfloat16* __restrict__ xl) {
    int j = blockIdx.x, tid = threadIdx.x;
    __shared__ float sbuf[32];
    __shared__ float s_mu, s_rstd;
    __shared__ float s_scale[HW];
    if (tid < HW) s_scale[tid] = 1.0f + Mv[j * HW + tid];
    __syncthreads();
    const float* base = xt + (size_t)j * (HW * CC);
    float sum = 0.f, sq = 0.f;
    for (int idx = tid; idx < HW * CC; idx += 256) {
        float v = base[idx] * s_scale[idx >> 9];
        sum += v; sq += v * v;
    }
    float ts = blockReduceSum256(sum, sbuf);
    __syncthreads();
    float tq = blockReduceSum256(sq, sbuf);
    if (tid == 0) {
        float mu = ts * (1.0f / (HW * CC));
        float var = tq * (1.0f / (HW * CC)) - mu * mu;
        s_mu = mu; s_rstd = rsqrtf(var + EPS_);
    }
    __syncthreads();
    float mu = s_mu, rstd = s_rstd;
    size_t ob = (size_t)j * (HW * CC);
    for (int idx = tid; idx < HW * CC; idx += 256) {
        int s = idx >> 9, c = idx & 511;
        float v = base[idx] * s_scale[s];
        float r = (v - mu) * rstd * gam[c * HW + s] + bet[c * HW + s];
        xln[ob + idx] = r;
        __nv_bfloat16 h = __float2bfloat16(r);
        xh[ob + idx] = h;
        xl[ob + idx] = __float2bfloat16(r - __bfloat162float(h));
    }
}

// ---------------- LN2 + output in NCHW (smem-transposed, fully coalesced) -----
__global__ __launch_bounds__(256) void ln2_kernel(const float* __restrict__ r2,
                                                  const float* __restrict__ gam,
                                                  const float* __restrict__ bet,
                                                  float* __restrict__ out) {
    int j = blockIdx.x, tid = threadIdx.x;
    __shared__ float sbuf[32];
    __shared__ float s_mu, s_rstd;
    __shared__ float t[128][49];
    const float* base = r2 + (size_t)j * (HW * CC);
    float sum = 0.f, sq = 0.f;
    for (int idx = tid; idx < HW * CC; idx += 256) {
        float v = base[idx];
        sum += v; sq += v * v;
    }
    float ts = blockReduceSum256(sum, sbuf);
    __syncthreads();
    float tq = blockReduceSum256(sq, sbuf);
    if (tid == 0) {
        float mu = ts * (1.0f / (HW * CC));
        float var = tq * (1.0f / (HW * CC)) - mu * mu;
        s_mu = mu; s_rstd = rsqrtf(var + EPS_);
    }
    __syncthreads();
    float mu = s_mu, rstd = s_rstd;
    float* o = out + (size_t)j * (HW * CC);
    for (int c0 = 0; c0 < CC; c0 += 128) {
        __syncthreads();
        for (int idx = tid; idx < HW * 128; idx += 256) {
            int sp = idx >> 7, cc = idx & 127;
            t[cc][sp] = base[sp * CC + c0 + cc];
        }
        __syncthreads();
        for (int idx = tid; idx < 128 * HW; idx += 256) {
            int cc = idx / HW, sp = idx % HW;
            int oi = (c0 + cc) * HW + sp;
            o[oi] = (t[cc][sp] - mu) * rstd * gam[oi] + bet[oi];
        }
    }
}

// ---------------- launcher ----------------------------------------------------
extern "C" void kernel_launch(void* const* d_in, const int* in_sizes, int n_in,
                              void* d_out, int out_size) {
    const float* x       = (const float*)d_in[0];
    const float* theta_w = (const float*)d_in[1];
    const float* theta_b = (const float*)d_in[2];
    const float* phi_w   = (const float*)d_in[3];
    const float* phi_b   = (const float*)d_in[4];
    const float* conv1_w = (const float*)d_in[5];
    const float* conv2_w = (const float*)d_in[6];
    const float* ln1_g   = (const float*)d_in[7];
    const float* ln1_b   = (const float*)d_in[8];
    const float* ln2_g   = (const float*)d_in[9];
    const float* ln2_b   = (const float*)d_in[10];
    float* out = (float*)d_out;

    float *xt, *phi, *F, *Mv, *xln, *r2;
    __nv_bfloat16 *xth, *xtl, *wh, *wl, *thh, *thl, *pph, *ppl, *xlnh, *xlnl, *y1h, *y1l;
    cudaGetSymbolAddress((void**)&xt,   g_xt);
    cudaGetSymbolAddress((void**)&xth,  g_xth);
    cudaGetSymbolAddress((void**)&xtl,  g_xtl);
    cudaGetSymbolAddress((void**)&wh,   g_wh);
    cudaGetSymbolAddress((void**)&wl,   g_wl);
    cudaGetSymbolAddress((void**)&thh,  g_thh);
    cudaGetSymbolAddress((void**)&thl,  g_thl);
    cudaGetSymbolAddress((void**)&phi,  g_phi);
    cudaGetSymbolAddress((void**)&pph,  g_pph);
    cudaGetSymbolAddress((void**)&ppl,  g_ppl);
    cudaGetSymbolAddress((void**)&F,    g_F);
    cudaGetSymbolAddress((void**)&Mv,   g_M);
    cudaGetSymbolAddress((void**)&xln,  g_xln);
    cudaGetSymbolAddress((void**)&xlnh, g_xlnh);
    cudaGetSymbolAddress((void**)&xlnl, g_xlnl);
    cudaGetSymbolAddress((void**)&y1h,  g_y1h);
    cudaGetSymbolAddress((void**)&y1l,  g_y1l);
    cudaGetSymbolAddress((void**)&r2,   g_r2);

    cudaFuncSetAttribute(tgemm_dual_kernel,
        cudaFuncAttributeMaxDynamicSharedMemorySize, DSMEM_BYTES);
    cudaFuncSetAttribute(tgemm_kernel<false, false, false, true, false>,
        cudaFuncAttributeMaxDynamicSharedMemorySize, DSMEM_BYTES);
    cudaFuncSetAttribute(tgemm_kernel<false, true, false, false, true>,
        cudaFuncAttributeMaxDynamicSharedMemorySize, DSMEM_BYTES);
    cudaFuncSetAttribute(tgemm_kernel<false, false, true, true, false>,
        cudaFuncAttributeMaxDynamicSharedMemorySize, DSMEM_BYTES);

    const int W1 = W1SZ, W2 = W2SZ;
    const int SPLIT_TOTAL = 2 * W1 + 2 * W2;

    transpose_kernel<<<dim3(NB, 4), 256>>>(x, xt, xth, xtl);
    split_all_kernel<<<SPLIT_TOTAL / 256, 256>>>(theta_w, phi_w, conv1_w, conv2_w, wh, wl);

    // theta (bf16-split out) & phi (f32 out): [3072,512]@[256,512]^T
    tgemm_dual_kernel<<<dim3(CI_ / 64, PP / 128, 2), 128, DSMEM_BYTES>>>(
        xth, xtl, wh, wl, wh + W1, wl + W1, theta_b, phi_b, thh, thl, phi, CI_, CC);
    pool_kernel<<<dim3(NM, NB), 256>>>(phi, pph, ppl);
    // F = theta @ phip^T : [3072,256]@[768,256]^T
    tgemm_kernel<false, false, false, true, false><<<dim3(NCF / 64, PP / 128), 128, DSMEM_BYTES>>>(
        thh, thl, pph, ppl, nullptr, nullptr, F, nullptr, nullptr, NCF, CI_);
    reduceM_kernel<<<PP / 8, 256>>>(F, Mv);
    ln1_kernel<<<NB, 256>>>(xt, Mv, ln1_g, ln1_b, xln, xlnh, xlnl);
    // y1 = relu(xln @ conv1_w^T) -> bf16 split
    tgemm_kernel<false, true, false, false, true><<<dim3(CC / 64, PP / 128), 128, DSMEM_BYTES>>>(
        xlnh, xlnl, wh + 2 * W1, wl + 2 * W1, nullptr, nullptr, nullptr, y1h, y1l, CC, CC);
    // r2 = xln + y1 @ conv2_w^T -> f32
    tgemm_kernel<false, false, true, true, false><<<dim3(CC / 64, PP / 128), 128, DSMEM_BYTES>>>(
        y1h, y1l, wh + 2 * W1 + W2, wl + 2 * W1 + W2, nullptr, xln, r2, nullptr, nullptr, CC, CC);
    ln2_kernel<<<NB, 256>>>(r2, ln2_g, ln2_b, out);
}

// round 11
// speedup vs baseline: 1.1955x; 1.1583x over previous
#include <cuda_runtime.h>
#include <cuda_fp16.h>
#include <cstdint>
#include <math.h>

// Problem constants
#define NB   64
#define CC   512
#define CI_  256
#define HH   12
#define WW   4
#define HW   48
#define PP   (NB*HW)     // 3072
#define NM   12
#define NCF  (NB*NM)     // 768
#define EPS_ 1e-5f
#define W1SZ (CI_*CC)    // 131072
#define W2SZ (CC*CC)     // 262144

// ---------------- scratch (device globals) ------------------------------------
__device__ float   g_xt  [PP * CC];
__device__ __half  g_xth [PP * CC];
__device__ __half  g_xtl [PP * CC];
__device__ __half  g_wh  [2 * W1SZ + 2 * W2SZ];   // single-half weights (B role)
__device__ __half  g_thh [PP * CI_];
__device__ __half  g_thl [PP * CI_];
__device__ float   g_phi [PP * CI_];
__device__ __half  g_pph [NCF * CI_];             // single-half phip (B role)
__device__ float   g_F   [PP * NCF];
__device__ float   g_M   [PP];
__device__ float   g_xln [PP * CC];
__device__ __half  g_xlnh[PP * CC];
__device__ __half  g_xlnl[PP * CC];
__device__ __half  g_y1h [PP * CC];
__device__ __half  g_y1l [PP * CC];
__device__ float   g_r2  [PP * CC];

// ---------------- primitives ---------------------------------------------------
__device__ __forceinline__ uint32_t smem_u32(const void* p) {
    uint32_t a;
    asm("{ .reg .u64 t; cvta.to.shared.u64 t, %1; cvt.u32.u64 %0, t; }"
        : "=r"(a) : "l"(p));
    return a;
}
__device__ __forceinline__ void ldsm4(uint32_t* r, uint32_t addr) {
    asm volatile("ldmatrix.sync.aligned.m8n8.x4.shared.b16 {%0,%1,%2,%3}, [%4];"
                 : "=r"(r[0]), "=r"(r[1]), "=r"(r[2]), "=r"(r[3]) : "r"(addr));
}
__device__ __forceinline__ void mma_f16(float* d, const uint32_t* a, const uint32_t* b) {
    asm volatile("mma.sync.aligned.m16n8k16.row.col.f32.f16.f16.f32 "
                 "{%0,%1,%2,%3}, {%4,%5,%6,%7}, {%8,%9}, {%0,%1,%2,%3};"
                 : "+f"(d[0]), "+f"(d[1]), "+f"(d[2]), "+f"(d[3])
                 : "r"(a[0]), "r"(a[1]), "r"(a[2]), "r"(a[3]), "r"(b[0]), "r"(b[1]));
}
__device__ __forceinline__ void cp16(uint32_t s, const void* g) {
    asm volatile("cp.async.cg.shared.global [%0], [%1], 16;" :: "r"(s), "l"(g) : "memory");
}
__device__ __forceinline__ void cp_commit() {
    asm volatile("cp.async.commit_group;" ::: "memory");
}
template<int N> __device__ __forceinline__ void cp_wait() {
    asm volatile("cp.async.wait_group %0;" :: "n"(N) : "memory");
}

// smem: stage = A hi(16K) + A lo(16K) + B(8K) = 40K; double-buffered = 80K
#define STG_BYTES   40960
#define DSMEM_BYTES 81920

// ---------------- tensor-core GEMM, cp.async double-buffered ------------------
// C[m,n] = A[m,:]·B[n,:] with A ~ Ah+Al (fp16 split), B single fp16 (2-MMA).
// Tile 128x64, BK=64, 128 threads (4 warps, 2x2 grid, 64x32 per warp).
template<bool BIAS, bool RELU, bool ADD, bool EMITF, bool EMITS>
__device__ __forceinline__ void tgemm_body(
    const __half* __restrict__ Ah, const __half* __restrict__ Al,
    const __half* __restrict__ Bh,
    const float* __restrict__ bias, const float* __restrict__ addsrc,
    float* __restrict__ outf,
    __half* __restrict__ oh, __half* __restrict__ ol,
    int Nc, int K, int m0, int n0, uint8_t* dsm)
{
    const int tid  = threadIdx.x;
    const int lane = tid & 31, wid = tid >> 5;
    const int wm = wid & 1, wn = wid >> 1;       // 2x2 warp grid
    const uint32_t sbase = smem_u32(dsm);

    const int rA  = (lane & 7) + ((lane >> 3) & 1) * 8;
    const int kgA = (lane >> 4) & 1;
    const int rB  = (lane & 7) + ((lane >> 4) & 1) * 8;
    const int kgB = (lane >> 3) & 1;
    const int l7  = lane & 7;

    float acc[4][4][4];                          // 64x32 per warp
    #pragma unroll
    for (int mf = 0; mf < 4; mf++)
        #pragma unroll
        for (int nf = 0; nf < 4; nf++)
            #pragma unroll
            for (int q = 0; q < 4; q++) acc[mf][nf][q] = 0.f;

    const int nch = K >> 6;

    auto stage = [&](int ch, int b) {
        const int k0 = ch << 6;
        const uint32_t abase = sbase + b * STG_BYTES;
        #pragma unroll
        for (int h = 0; h < 2; h++) {            // A hi/lo: 128 rows x 8 groups
            const __half* src = h ? Al : Ah;
            uint32_t dst = abase + h * 16384;
            #pragma unroll
            for (int i = 0; i < 8; i++) {
                int t = tid + i * 128;           // 0..1023
                int r = t >> 3, g = t & 7;
                cp16(dst + r * 128 + ((g ^ (r & 7)) << 4),
                     src + (size_t)(m0 + r) * K + k0 + g * 8);
            }
        }
        {                                        // B single: 64 rows x 8 groups
            uint32_t dst = abase + 32768;
            #pragma unroll
            for (int i = 0; i < 4; i++) {
                int t = tid + i * 128;           // 0..511
                int r = t >> 3, g = t & 7;
                cp16(dst + r * 128 + ((g ^ (r & 7)) << 4),
                     Bh + (size_t)(n0 + r) * K + k0 + g * 8);
            }
        }
        cp_commit();
    };

    stage(0, 0);
    for (int ch = 0; ch < nch; ch++) {
        const int buf = ch & 1;
        if (ch + 1 < nch) { stage(ch + 1, buf ^ 1); cp_wait<1>(); }
        else              { cp_wait<0>(); }
        __syncthreads();
        const uint32_t sAu = sbase + buf * STG_BYTES;
        const uint32_t sBu = sAu + 32768;
        #pragma unroll
        for (int ks = 0; ks < 4; ks++) {
            uint32_t a[4][2][4], b[2][4];
            const int xA = ((ks * 2 + kgA) ^ l7) << 4;
            const int xB = ((ks * 2 + kgB) ^ l7) << 4;
            #pragma unroll
            for (int mf = 0; mf < 4; mf++) {
                int row = wm * 64 + mf * 16 + rA;
                #pragma unroll
                for (int h = 0; h < 2; h++)
                    ldsm4(a[mf][h], sAu + h * 16384 + row * 128 + xA);
            }
            #pragma unroll
            for (int np = 0; np < 2; np++) {
                int row = wn * 32 + np * 16 + rB;
                ldsm4(b[np], sBu + row * 128 + xB);
            }
            #pragma unroll
            for (int mf = 0; mf < 4; mf++)
                #pragma unroll
                for (int nf = 0; nf < 4; nf++) {
                    int np = nf >> 1, sub = (nf & 1) << 1;
                    mma_f16(acc[mf][nf], a[mf][0], &b[np][sub]);  // Ah*B
                    mma_f16(acc[mf][nf], a[mf][1], &b[np][sub]);  // Al*B
                }
        }
        __syncthreads();
    }
    // ---- epilogue ----
    const int mrow0 = m0 + wm * 64 + (lane >> 2);
    const int col0  = n0 + wn * 32 + (lane & 3) * 2;
    #pragma unroll
    for (int mf = 0; mf < 4; mf++)
        #pragma unroll
        for (int nf = 0; nf < 4; nf++)
            #pragma unroll
            for (int hf = 0; hf < 2; hf++) {
                int row = mrow0 + mf * 16 + hf * 8;
                int col = col0 + nf * 8;
                float vx = acc[mf][nf][hf * 2];
                float vy = acc[mf][nf][hf * 2 + 1];
                if (BIAS) { vx += bias[col]; vy += bias[col + 1]; }
                if (RELU) { vx = fmaxf(vx, 0.f); vy = fmaxf(vy, 0.f); }
                if (ADD) {
                    const float2 a2 = *(const float2*)&addsrc[(size_t)row * Nc + col];
                    vx += a2.x; vy += a2.y;
                }
                if (EMITF) *(float2*)&outf[(size_t)row * Nc + col] = make_float2(vx, vy);
                if (EMITS) {
                    __half hx = __float2half_rn(vx);
                    __half hy = __float2half_rn(vy);
                    __half lx = __float2half_rn(vx - __half2float(hx));
                    __half ly = __float2half_rn(vy - __half2float(hy));
                    *(__half2*)&oh[(size_t)row * Nc + col] = __halves2half2(hx, hy);
                    *(__half2*)&ol[(size_t)row * Nc + col] = __halves2half2(lx, ly);
                }
            }
}

template<bool BIAS, bool RELU, bool ADD, bool EMITF, bool EMITS>
__global__ __launch_bounds__(128) void tgemm_kernel(
    const __half* __restrict__ Ah, const __half* __restrict__ Al,
    const __half* __restrict__ Bh,
    const float* __restrict__ bias, const float* __restrict__ addsrc,
    float* __restrict__ outf,
    __half* __restrict__ oh, __half* __restrict__ ol,
    int Nc, int K)
{
    extern __shared__ uint8_t dsm[];
    tgemm_body<BIAS, RELU, ADD, EMITF, EMITS>(Ah, Al, Bh, bias, addsrc,
        outf, oh, ol, Nc, K, blockIdx.y * 128, blockIdx.x * 64, dsm);
}

// dual projection: z=0 -> theta (half-split out), z=1 -> phi (f32 out)
__global__ __launch_bounds__(128) void tgemm_dual_kernel(
    const __half* __restrict__ Ah, const __half* __restrict__ Al,
    const __half* __restrict__ B0h, const __half* __restrict__ B1h,
    const float* __restrict__ bias0, const float* __restrict__ bias1,
    __half* __restrict__ thh, __half* __restrict__ thl,
    float* __restrict__ phi, int Nc, int K)
{
    extern __shared__ uint8_t dsm[];
    if (blockIdx.z == 0)
        tgemm_body<true, false, false, false, true>(Ah, Al, B0h, bias0, nullptr,
            nullptr, thh, thl, Nc, K, blockIdx.y * 128, blockIdx.x * 64, dsm);
    else
        tgemm_body<true, false, false, true, false>(Ah, Al, B1h, bias1, nullptr,
            phi, nullptr, nullptr, Nc, K, blockIdx.y * 128, blockIdx.x * 64, dsm);
}

// ---------------- transpose + split: x[N,C,H,W] -> xt, xt_hi, xt_lo -----------
__global__ __launch_bounds__(256) void transpose_kernel(const float* __restrict__ x,
                                                        float* __restrict__ xt,
                                                        __half* __restrict__ xh,
                                                        __half* __restrict__ xl) {
    int j  = blockIdx.x;
    int c0 = blockIdx.y * 128;
    __shared__ float t[128][49];
    int tid = threadIdx.x;
    const float* xb = x + j * (CC * HW);
    for (int idx = tid; idx < 128 * HW; idx += 256) {
        int cc = idx / HW, s = idx % HW;
        t[cc][s] = xb[(c0 + cc) * HW + s];
    }
    __syncthreads();
    size_t ob = (size_t)j * HW * CC;
    for (int idx = tid; idx < HW * 128; idx += 256) {
        int s = idx >> 7, cc = idx & 127;
        float v = t[cc][s];
        size_t o = ob + s * CC + c0 + cc;
        xt[o] = v;
        __half h = __float2half_rn(v);
        xh[o] = h;
        xl[o] = __float2half_rn(v - __half2float(h));
    }
}

// ---------------- all-weights fp32 -> single fp16 (one launch) ----------------
__global__ __launch_bounds__(256) void split_all_kernel(const float* __restrict__ w0,
                                                        const float* __restrict__ w1,
                                                        const float* __restrict__ w2,
                                                        const float* __restrict__ w3,
                                                        __half* __restrict__ h) {
    int i = blockIdx.x * 256 + threadIdx.x;   // total 2*W1SZ + 2*W2SZ
    const float* src; int off;
    if (i < W1SZ)                  { src = w0; off = i; }
    else if (i < 2 * W1SZ)         { src = w1; off = i - W1SZ; }
    else if (i < 2 * W1SZ + W2SZ)  { src = w2; off = i - 2 * W1SZ; }
    else                           { src = w3; off = i - 2 * W1SZ - W2SZ; }
    h[i] = __float2half_rn(src[off]);
}

// ---------------- maxpool 2x2 on phi -> phip (single half) --------------------
__global__ __launch_bounds__(256) void pool_kernel(const float* __restrict__ phi,
                                                   __half* __restrict__ ph) {
    int m = blockIdx.x, i = blockIdx.y;
    int c = threadIdx.x;   // 256 = CI
    int phh = m >> 1, pw = m & 1;
    int s0 = (2 * phh) * WW + 2 * pw;
    const float* b = phi + (size_t)(i * HW) * CI_ + c;
    float v = b[(size_t)s0 * CI_];
    v = fmaxf(v, b[(size_t)(s0 + 1) * CI_]);
    v = fmaxf(v, b[(size_t)(s0 + WW) * CI_]);
    v = fmaxf(v, b[(size_t)(s0 + WW + 1) * CI_]);
    ph[(size_t)(i * NM + m) * CI_ + c] = __float2half_rn(v);
}

// ---------------- reduce F -> M (float4-vectorized group max) -----------------
__global__ __launch_bounds__(256) void reduceM_kernel(const float* __restrict__ F,
                                                      float* __restrict__ Mv) {
    int p = blockIdx.x * 8 + (threadIdx.x >> 5);
    int lane = threadIdx.x & 31;
    const float4* row4 = (const float4*)(F + (size_t)p * NCF);  // 192 float4s
    float s = 0.f;
    #pragma unroll
    for (int g = lane; g < NB; g += 32) {
        float4 a = row4[3 * g], b = row4[3 * g + 1], c = row4[3 * g + 2];
        float v = fmaxf(fmaxf(fmaxf(a.x, a.y), fmaxf(a.z, a.w)),
                  fmaxf(fmaxf(fmaxf(b.x, b.y), fmaxf(b.z, b.w)),
                        fmaxf(fmaxf(c.x, c.y), fmaxf(c.z, c.w))));
        s += v;
    }
    #pragma unroll
    for (int o = 16; o > 0; o >>= 1) s += __shfl_down_sync(0xffffffffu, s, o);
    if (lane == 0) Mv[p] = s * (1.0f / 12.0f);
}

// ---------------- block reduction helper --------------------------------------
__device__ __forceinline__ float blockReduceSum256(float v, float* sbuf) {
    #pragma unroll
    for (int o = 16; o > 0; o >>= 1) v += __shfl_down_sync(0xffffffffu, v, o);
    int lane = threadIdx.x & 31, w = threadIdx.x >> 5;
    if (lane == 0) sbuf[w] = v;
    __syncthreads();
    v = (threadIdx.x < 8) ? sbuf[threadIdx.x] : 0.f;
    if (w == 0) {
        #pragma unroll
        for (int o = 4; o > 0; o >>= 1) v += __shfl_down_sync(0xffu, v, o);
    }
    return v;
}

// ---------------- res1 + LN1 (emits f32 + hi/lo half split) -------------------
__global__ __launch_bounds__(256) void ln1_kernel(const float* __restrict__ xt,
                                                  const float* __restrict__ Mv,
                                                  const float* __restrict__ gam,
                                                  const float* __restrict__ bet,
                                                  float* __restrict__ xln,
                                                  __half* __restrict__ xh,
                                                  __half* __restrict__ xl) {
    int j = blockIdx.x, tid = threadIdx.x;
    __shared__ float sbuf[32];
    __shared__ float s_mu, s_rstd;
    __shared__ float s_scale[HW];
    if (tid < HW) s_scale[tid] = 1.0f + Mv[j * HW + tid];
    __syncthreads();
    const float* base = xt + (size_t)j * (HW * CC);
    float sum = 0.f, sq = 0.f;
    for (int idx = tid; idx < HW * CC; idx += 256) {
        float v = base[idx] * s_scale[idx >> 9];
        sum += v; sq += v * v;
    }
    float ts = blockReduceSum256(sum, sbuf);
    __syncthreads();
    float tq = blockReduceSum256(sq, sbuf);
    if (tid == 0) {
        float mu = ts * (1.0f / (HW * CC));
        float var = tq * (1.0f / (HW * CC)) - mu * mu;
        s_mu = mu; s_rstd = rsqrtf(var + EPS_);
    }
    __syncthreads();
    float mu = s_mu, rstd = s_rstd;
    size_t ob = (size_t)j * (HW * CC);
    for (int idx = tid; idx < HW * CC; idx += 256) {
        int s = idx >> 9, c = idx & 511;
        float v = base[idx] * s_scale[s];
        float r = (v - mu) * rstd * gam[c * HW + s] + bet[c * HW + s];
        xln[ob + idx] = r;
        __half h = __float2half_rn(r);
        xh[ob + idx] = h;
        xl[ob + idx] = __float2half_rn(r - __half2float(h));
    }
}

// ---------------- LN2 + output in NCHW (smem-transposed, fully coalesced) -----
__global__ __launch_bounds__(256) void ln2_kernel(const float* __restrict__ r2,
                                                  const float* __restrict__ gam,
                                                  const float* __restrict__ bet,
                                                  float* __restrict__ out) {
    int j = blockIdx.x, tid = threadIdx.x;
    __shared__ float sbuf[32];
    __shared__ float s_mu, s_rstd;
    __shared__ float t[128][49];
    const float* base = r2 + (size_t)j * (HW * CC);
    float sum = 0.f, sq = 0.f;
    for (int idx = tid; idx < HW * CC; idx += 256) {
        float v = base[idx];
        sum += v; sq += v * v;
    }
    float ts = blockReduceSum256(sum, sbuf);
    __syncthreads();
    float tq = blockReduceSum256(sq, sbuf);
    if (tid == 0) {
        float mu = ts * (1.0f / (HW * CC));
        float var = tq * (1.0f / (HW * CC)) - mu * mu;
        s_mu = mu; s_rstd = rsqrtf(var + EPS_);
    }
    __syncthreads();
    float mu = s_mu, rstd = s_rstd;
    float* o = out + (size_t)j * (HW * CC);
    for (int c0 = 0; c0 < CC; c0 += 128) {
        __syncthreads();
        for (int idx = tid; idx < HW * 128; idx += 256) {
            int sp = idx >> 7, cc = idx & 127;
            t[cc][sp] = base[sp * CC + c0 + cc];
        }
        __syncthreads();
        for (int idx = tid; idx < 128 * HW; idx += 256) {
            int cc = idx / HW, sp = idx % HW;
            int oi = (c0 + cc) * HW + sp;
            o[oi] = (t[cc][sp] - mu) * rstd * gam[oi] + bet[oi];
        }
    }
}

// ---------------- launcher ----------------------------------------------------
extern "C" void kernel_launch(void* const* d_in, const int* in_sizes, int n_in,
                              void* d_out, int out_size) {
    const float* x       = (const float*)d_in[0];
    const float* theta_w = (const float*)d_in[1];
    const float* theta_b = (const float*)d_in[2];
    const float* phi_w   = (const float*)d_in[3];
    const float* phi_b   = (const float*)d_in[4];
    const float* conv1_w = (const float*)d_in[5];
    const float* conv2_w = (const float*)d_in[6];
    const float* ln1_g   = (const float*)d_in[7];
    const float* ln1_b   = (const float*)d_in[8];
    const float* ln2_g   = (const float*)d_in[9];
    const float* ln2_b   = (const float*)d_in[10];
    float* out = (float*)d_out;

    float *xt, *phi, *F, *Mv, *xln, *r2;
    __half *xth, *xtl, *wh, *thh, *thl, *pph, *xlnh, *xlnl, *y1h, *y1l;
    cudaGetSymbolAddress((void**)&xt,   g_xt);
    cudaGetSymbolAddress((void**)&xth,  g_xth);
    cudaGetSymbolAddress((void**)&xtl,  g_xtl);
    cudaGetSymbolAddress((void**)&wh,   g_wh);
    cudaGetSymbolAddress((void**)&thh,  g_thh);
    cudaGetSymbolAddress((void**)&thl,  g_thl);
    cudaGetSymbolAddress((void**)&phi,  g_phi);
    cudaGetSymbolAddress((void**)&pph,  g_pph);
    cudaGetSymbolAddress((void**)&F,    g_F);
    cudaGetSymbolAddress((void**)&Mv,   g_M);
    cudaGetSymbolAddress((void**)&xln,  g_xln);
    cudaGetSymbolAddress((void**)&xlnh, g_xlnh);
    cudaGetSymbolAddress((void**)&xlnl, g_xlnl);
    cudaGetSymbolAddress((void**)&y1h,  g_y1h);
    cudaGetSymbolAddress((void**)&y1l,  g_y1l);
    cudaGetSymbolAddress((void**)&r2,   g_r2);

    cudaFuncSetAttribute(tgemm_dual_kernel,
        cudaFuncAttributeMaxDynamicSharedMemorySize, DSMEM_BYTES);
    cudaFuncSetAttribute(tgemm_kernel<false, false, false, true, false>,
        cudaFuncAttributeMaxDynamicSharedMemorySize, DSMEM_BYTES);
    cudaFuncSetAttribute(tgemm_kernel<false, true, false, false, true>,
        cudaFuncAttributeMaxDynamicSharedMemorySize, DSMEM_BYTES);
    cudaFuncSetAttribute(tgemm_kernel<false, false, true, true, false>,
        cudaFuncAttributeMaxDynamicSharedMemorySize, DSMEM_BYTES);

    const int W1 = W1SZ, W2 = W2SZ;
    const int SPLIT_TOTAL = 2 * W1 + 2 * W2;

    transpose_kernel<<<dim3(NB, 4), 256>>>(x, xt, xth, xtl);
    split_all_kernel<<<SPLIT_TOTAL / 256, 256>>>(theta_w, phi_w, conv1_w, conv2_w, wh);

    // theta (half-split out) & phi (f32 out): [3072,512]@[256,512]^T
    tgemm_dual_kernel<<<dim3(CI_ / 64, PP / 128, 2), 128, DSMEM_BYTES>>>(
        xth, xtl, wh, wh + W1, theta_b, phi_b, thh, thl, phi, CI_, CC);
    pool_kernel<<<dim3(NM, NB), 256>>>(phi, pph);
    // F = theta @ phip^T : [3072,256]@[768,256]^T
    tgemm_kernel<false, false, false, true, false><<<dim3(NCF / 64, PP / 128), 128, DSMEM_BYTES>>>(
        thh, thl, pph, nullptr, nullptr, F, nullptr, nullptr, NCF, CI_);
    reduceM_kernel<<<PP / 8, 256>>>(F, Mv);
    ln1_kernel<<<NB, 256>>>(xt, Mv, ln1_g, ln1_b, xln, xlnh, xlnl);
    // y1 = relu(xln @ conv1_w^T) -> half split
    tgemm_kernel<false, true, false, false, true><<<dim3(CC / 64, PP / 128), 128, DSMEM_BYTES>>>(
        xlnh, xlnl, wh + 2 * W1, nullptr, nullptr, nullptr, y1h, y1l, CC, CC);
    // r2 = xln + y1 @ conv2_w^T -> f32
    tgemm_kernel<false, false, true, true, false><<<dim3(CC / 64, PP / 128), 128, DSMEM_BYTES>>>(
        y1h, y1l, wh + 2 * W1 + W2, nullptr, xln, r2, nullptr, nullptr, CC, CC);
    ln2_kernel<<<NB, 256>>>(r2, ln2_g, ln2_b, out);
}

// round 12
// speedup vs baseline: 1.4145x; 1.1832x over previous
#include <cuda_runtime.h>
#include <cuda_fp16.h>
#include <cstdint>
#include <math.h>

// Problem constants
#define NB   64
#define CC   512
#define CI_  256
#define HH   12
#define WW   4
#define HW   48
#define PP   (NB*HW)     // 3072
#define NM   12
#define NCF  (NB*NM)     // 768
#define EPS_ 1e-5f
#define W1SZ (CI_*CC)    // 131072
#define W2SZ (CC*CC)     // 262144

// ---------------- scratch (device globals) ------------------------------------
__device__ float   g_xt  [PP * CC];
__device__ __half  g_xth [PP * CC];
__device__ __half  g_wh  [2 * W1SZ + 2 * W2SZ];   // fp16 weights (B role)
__device__ __half  g_thh [PP * CI_];
__device__ float   g_phi [PP * CI_];
__device__ __half  g_pph [NCF * CI_];
__device__ float   g_F   [PP * NCF];
__device__ float   g_M   [PP];
__device__ float   g_xln [PP * CC];
__device__ __half  g_xlnh[PP * CC];
__device__ __half  g_y1h [PP * CC];
__device__ float   g_r2  [PP * CC];

// ---------------- primitives ---------------------------------------------------
__device__ __forceinline__ uint32_t smem_u32(const void* p) {
    uint32_t a;
    asm("{ .reg .u64 t; cvta.to.shared.u64 t, %1; cvt.u32.u64 %0, t; }"
        : "=r"(a) : "l"(p));
    return a;
}
__device__ __forceinline__ void ldsm4(uint32_t* r, uint32_t addr) {
    asm volatile("ldmatrix.sync.aligned.m8n8.x4.shared.b16 {%0,%1,%2,%3}, [%4];"
                 : "=r"(r[0]), "=r"(r[1]), "=r"(r[2]), "=r"(r[3]) : "r"(addr));
}
__device__ __forceinline__ void mma_f16(float* d, const uint32_t* a, const uint32_t* b) {
    asm volatile("mma.sync.aligned.m16n8k16.row.col.f32.f16.f16.f32 "
                 "{%0,%1,%2,%3}, {%4,%5,%6,%7}, {%8,%9}, {%0,%1,%2,%3};"
                 : "+f"(d[0]), "+f"(d[1]), "+f"(d[2]), "+f"(d[3])
                 : "r"(a[0]), "r"(a[1]), "r"(a[2]), "r"(a[3]), "r"(b[0]), "r"(b[1]));
}
__device__ __forceinline__ void cp16(uint32_t s, const void* g) {
    asm volatile("cp.async.cg.shared.global [%0], [%1], 16;" :: "r"(s), "l"(g) : "memory");
}
__device__ __forceinline__ void cp_commit() {
    asm volatile("cp.async.commit_group;" ::: "memory");
}
template<int N> __device__ __forceinline__ void cp_wait() {
    asm volatile("cp.async.wait_group %0;" :: "n"(N) : "memory");
}

// smem: stage = A(16K) + B(8K) = 24K; double-buffered = 48K
#define STG_BYTES   24576
#define DSMEM_BYTES 49152

// ---------------- tensor-core GEMM, cp.async double-buffered ------------------
// C[m,n] = A[m,:]·B[n,:], pure fp16 operands (1 MMA per tile-op).
// Tile 128x64, BK=64, 128 threads (4 warps, 2x2 grid, 64x32 per warp).
template<bool BIAS, bool RELU, bool ADD, bool EMITF, bool EMITS>
__device__ __forceinline__ void tgemm_body(
    const __half* __restrict__ Ah, const __half* __restrict__ Bh,
    const float* __restrict__ bias, const float* __restrict__ addsrc,
    float* __restrict__ outf, __half* __restrict__ oh,
    int Nc, int K, int m0, int n0, uint8_t* dsm)
{
    const int tid  = threadIdx.x;
    const int lane = tid & 31, wid = tid >> 5;
    const int wm = wid & 1, wn = wid >> 1;       // 2x2 warp grid
    const uint32_t sbase = smem_u32(dsm);

    const int rA  = (lane & 7) + ((lane >> 3) & 1) * 8;
    const int kgA = (lane >> 4) & 1;
    const int rB  = (lane & 7) + ((lane >> 4) & 1) * 8;
    const int kgB = (lane >> 3) & 1;
    const int l7  = lane & 7;

    float acc[4][4][4];                          // 64x32 per warp
    #pragma unroll
    for (int mf = 0; mf < 4; mf++)
        #pragma unroll
        for (int nf = 0; nf < 4; nf++)
            #pragma unroll
            for (int q = 0; q < 4; q++) acc[mf][nf][q] = 0.f;

    const int nch = K >> 6;

    auto stage = [&](int ch, int b) {
        const int k0 = ch << 6;
        const uint32_t abase = sbase + b * STG_BYTES;
        #pragma unroll
        for (int i = 0; i < 8; i++) {            // A: 128 rows x 8 groups
            int t = tid + i * 128;               // 0..1023
            int r = t >> 3, g = t & 7;
            cp16(abase + r * 128 + ((g ^ (r & 7)) << 4),
                 Ah + (size_t)(m0 + r) * K + k0 + g * 8);
        }
        {                                        // B: 64 rows x 8 groups
            uint32_t dst = abase + 16384;
            #pragma unroll
            for (int i = 0; i < 4; i++) {
                int t = tid + i * 128;           // 0..511
                int r = t >> 3, g = t & 7;
                cp16(dst + r * 128 + ((g ^ (r & 7)) << 4),
                     Bh + (size_t)(n0 + r) * K + k0 + g * 8);
            }
        }
        cp_commit();
    };

    stage(0, 0);
    for (int ch = 0; ch < nch; ch++) {
        const int buf = ch & 1;
        if (ch + 1 < nch) { stage(ch + 1, buf ^ 1); cp_wait<1>(); }
        else              { cp_wait<0>(); }
        __syncthreads();
        const uint32_t sAu = sbase + buf * STG_BYTES;
        const uint32_t sBu = sAu + 16384;
        #pragma unroll
        for (int ks = 0; ks < 4; ks++) {
            uint32_t a[4][4], b[2][4];
            const int xA = ((ks * 2 + kgA) ^ l7) << 4;
            const int xB = ((ks * 2 + kgB) ^ l7) << 4;
            #pragma unroll
            for (int mf = 0; mf < 4; mf++) {
                int row = wm * 64 + mf * 16 + rA;
                ldsm4(a[mf], sAu + row * 128 + xA);
            }
            #pragma unroll
            for (int np = 0; np < 2; np++) {
                int row = wn * 32 + np * 16 + rB;
                ldsm4(b[np], sBu + row * 128 + xB);
            }
            #pragma unroll
            for (int mf = 0; mf < 4; mf++)
                #pragma unroll
                for (int nf = 0; nf < 4; nf++) {
                    int np = nf >> 1, sub = (nf & 1) << 1;
                    mma_f16(acc[mf][nf], a[mf], &b[np][sub]);
                }
        }
        __syncthreads();
    }
    // ---- epilogue ----
    const int mrow0 = m0 + wm * 64 + (lane >> 2);
    const int col0  = n0 + wn * 32 + (lane & 3) * 2;
    #pragma unroll
    for (int mf = 0; mf < 4; mf++)
        #pragma unroll
        for (int nf = 0; nf < 4; nf++)
            #pragma unroll
            for (int hf = 0; hf < 2; hf++) {
                int row = mrow0 + mf * 16 + hf * 8;
                int col = col0 + nf * 8;
                float vx = acc[mf][nf][hf * 2];
                float vy = acc[mf][nf][hf * 2 + 1];
                if (BIAS) { vx += bias[col]; vy += bias[col + 1]; }
                if (RELU) { vx = fmaxf(vx, 0.f); vy = fmaxf(vy, 0.f); }
                if (ADD) {
                    const float2 a2 = *(const float2*)&addsrc[(size_t)row * Nc + col];
                    vx += a2.x; vy += a2.y;
                }
                if (EMITF) *(float2*)&outf[(size_t)row * Nc + col] = make_float2(vx, vy);
                if (EMITS)
                    *(__half2*)&oh[(size_t)row * Nc + col] =
                        __halves2half2(__float2half_rn(vx), __float2half_rn(vy));
            }
}

template<bool BIAS, bool RELU, bool ADD, bool EMITF, bool EMITS>
__global__ __launch_bounds__(128) void tgemm_kernel(
    const __half* __restrict__ Ah, const __half* __restrict__ Bh,
    const float* __restrict__ bias, const float* __restrict__ addsrc,
    float* __restrict__ outf, __half* __restrict__ oh,
    int Nc, int K)
{
    extern __shared__ uint8_t dsm[];
    tgemm_body<BIAS, RELU, ADD, EMITF, EMITS>(Ah, Bh, bias, addsrc,
        outf, oh, Nc, K, blockIdx.y * 128, blockIdx.x * 64, dsm);
}

// dual projection: z=0 -> theta (half out), z=1 -> phi (f32 out)
__global__ __launch_bounds__(128) void tgemm_dual_kernel(
    const __half* __restrict__ Ah,
    const __half* __restrict__ B0h, const __half* __restrict__ B1h,
    const float* __restrict__ bias0, const float* __restrict__ bias1,
    __half* __restrict__ thh, float* __restrict__ phi, int Nc, int K)
{
    extern __shared__ uint8_t dsm[];
    if (blockIdx.z == 0)
        tgemm_body<true, false, false, false, true>(Ah, B0h, bias0, nullptr,
            nullptr, thh, Nc, K, blockIdx.y * 128, blockIdx.x * 64, dsm);
    else
        tgemm_body<true, false, false, true, false>(Ah, B1h, bias1, nullptr,
            phi, nullptr, Nc, K, blockIdx.y * 128, blockIdx.x * 64, dsm);
}

// ---------------- transpose + fp16 cast: x[N,C,H,W] -> xt, xt_h ---------------
__global__ __launch_bounds__(256) void transpose_kernel(const float* __restrict__ x,
                                                        float* __restrict__ xt,
                                                        __half* __restrict__ xh) {
    int j  = blockIdx.x;
    int c0 = blockIdx.y * 128;
    __shared__ float t[128][49];
    int tid = threadIdx.x;
    const float* xb = x + j * (CC * HW);
    for (int idx = tid; idx < 128 * HW; idx += 256) {
        int cc = idx / HW, s = idx % HW;
        t[cc][s] = xb[(c0 + cc) * HW + s];
    }
    __syncthreads();
    size_t ob = (size_t)j * HW * CC;
    for (int idx = tid; idx < HW * 128; idx += 256) {
        int s = idx >> 7, cc = idx & 127;
        float v = t[cc][s];
        size_t o = ob + s * CC + c0 + cc;
        xt[o] = v;
        xh[o] = __float2half_rn(v);
    }
}

// ---------------- all-weights fp32 -> fp16 (one launch) -----------------------
__global__ __launch_bounds__(256) void split_all_kernel(const float* __restrict__ w0,
                                                        const float* __restrict__ w1,
                                                        const float* __restrict__ w2,
                                                        const float* __restrict__ w3,
                                                        __half* __restrict__ h) {
    int i = blockIdx.x * 256 + threadIdx.x;   // total 2*W1SZ + 2*W2SZ
    const float* src; int off;
    if (i < W1SZ)                  { src = w0; off = i; }
    else if (i < 2 * W1SZ)         { src = w1; off = i - W1SZ; }
    else if (i < 2 * W1SZ + W2SZ)  { src = w2; off = i - 2 * W1SZ; }
    else                           { src = w3; off = i - 2 * W1SZ - W2SZ; }
    h[i] = __float2half_rn(src[off]);
}

// ---------------- maxpool 2x2 on phi -> phip (fp16) ---------------------------
__global__ __launch_bounds__(256) void pool_kernel(const float* __restrict__ phi,
                                                   __half* __restrict__ ph) {
    int m = blockIdx.x, i = blockIdx.y;
    int c = threadIdx.x;   // 256 = CI
    int phh = m >> 1, pw = m & 1;
    int s0 = (2 * phh) * WW + 2 * pw;
    const float* b = phi + (size_t)(i * HW) * CI_ + c;
    float v = b[(size_t)s0 * CI_];
    v = fmaxf(v, b[(size_t)(s0 + 1) * CI_]);
    v = fmaxf(v, b[(size_t)(s0 + WW) * CI_]);
    v = fmaxf(v, b[(size_t)(s0 + WW + 1) * CI_]);
    ph[(size_t)(i * NM + m) * CI_ + c] = __float2half_rn(v);
}

// ---------------- reduce F -> M (float4-vectorized group max) -----------------
__global__ __launch_bounds__(256) void reduceM_kernel(const float* __restrict__ F,
                                                      float* __restrict__ Mv) {
    int p = blockIdx.x * 8 + (threadIdx.x >> 5);
    int lane = threadIdx.x & 31;
    const float4* row4 = (const float4*)(F + (size_t)p * NCF);  // 192 float4s
    float s = 0.f;
    #pragma unroll
    for (int g = lane; g < NB; g += 32) {
        float4 a = row4[3 * g], b = row4[3 * g + 1], c = row4[3 * g + 2];
        float v = fmaxf(fmaxf(fmaxf(a.x, a.y), fmaxf(a.z, a.w)),
                  fmaxf(fmaxf(fmaxf(b.x, b.y), fmaxf(b.z, b.w)),
                        fmaxf(fmaxf(c.x, c.y), fmaxf(c.z, c.w))));
        s += v;
    }
    #pragma unroll
    for (int o = 16; o > 0; o >>= 1) s += __shfl_down_sync(0xffffffffu, s, o);
    if (lane == 0) Mv[p] = s * (1.0f / 12.0f);
}

// ---------------- block reduction helper --------------------------------------
__device__ __forceinline__ float blockReduceSum256(float v, float* sbuf) {
    #pragma unroll
    for (int o = 16; o > 0; o >>= 1) v += __shfl_down_sync(0xffffffffu, v, o);
    int lane = threadIdx.x & 31, w = threadIdx.x >> 5;
    if (lane == 0) sbuf[w] = v;
    __syncthreads();
    v = (threadIdx.x < 8) ? sbuf[threadIdx.x] : 0.f;
    if (w == 0) {
        #pragma unroll
        for (int o = 4; o > 0; o >>= 1) v += __shfl_down_sync(0xffu, v, o);
    }
    return v;
}

// ---------------- res1 + LN1 (emits f32 + fp16) -------------------------------
__global__ __launch_bounds__(256) void ln1_kernel(const float* __restrict__ xt,
                                                  const float* __restrict__ Mv,
                                                  const float* __restrict__ gam,
                                                  const float* __restrict__ bet,
                                                  float* __restrict__ xln,
                                                  __half* __restrict__ xh) {
    int j = blockIdx.x, tid = threadIdx.x;
    __shared__ float sbuf[32];
    __shared__ float s_mu, s_rstd;
    __shared__ float s_scale[HW];
    if (tid < HW) s_scale[tid] = 1.0f + Mv[j * HW + tid];
    __syncthreads();
    const float* base = xt + (size_t)j * (HW * CC);
    float sum = 0.f, sq = 0.f;
    for (int idx = tid; idx < HW * CC; idx += 256) {
        float v = base[idx] * s_scale[idx >> 9];
        sum += v; sq += v * v;
    }
    float ts = blockReduceSum256(sum, sbuf);
    __syncthreads();
    float tq = blockReduceSum256(sq, sbuf);
    if (tid == 0) {
        float mu = ts * (1.0f / (HW * CC));
        float var = tq * (1.0f / (HW * CC)) - mu * mu;
        s_mu = mu; s_rstd = rsqrtf(var + EPS_);
    }
    __syncthreads();
    float mu = s_mu, rstd = s_rstd;
    size_t ob = (size_t)j * (HW * CC);
    for (int idx = tid; idx < HW * CC; idx += 256) {
        int s = idx >> 9, c = idx & 511;
        float v = base[idx] * s_scale[s];
        float r = (v - mu) * rstd * gam[c * HW + s] + bet[c * HW + s];
        xln[ob + idx] = r;
        xh[ob + idx] = __float2half_rn(r);
    }
}

// ---------------- LN2 + output in NCHW (smem-transposed, fully coalesced) -----
__global__ __launch_bounds__(256) void ln2_kernel(const float* __restrict__ r2,
                                                  const float* __restrict__ gam,
                                                  const float* __restrict__ bet,
                                                  float* __restrict__ out) {
    int j = blockIdx.x, tid = threadIdx.x;
    __shared__ float sbuf[32];
    __shared__ float s_mu, s_rstd;
    __shared__ float t[128][49];
    const float* base = r2 + (size_t)j * (HW * CC);
    float sum = 0.f, sq = 0.f;
    for (int idx = tid; idx < HW * CC; idx += 256) {
        float v = base[idx];
        sum += v; sq += v * v;
    }
    float ts = blockReduceSum256(sum, sbuf);
    __syncthreads();
    float tq = blockReduceSum256(sq, sbuf);
    if (tid == 0) {
        float mu = ts * (1.0f / (HW * CC));
        float var = tq * (1.0f / (HW * CC)) - mu * mu;
        s_mu = mu; s_rstd = rsqrtf(var + EPS_);
    }
    __syncthreads();
    float mu = s_mu, rstd = s_rstd;
    float* o = out + (size_t)j * (HW * CC);
    for (int c0 = 0; c0 < CC; c0 += 128) {
        __syncthreads();
        for (int idx = tid; idx < HW * 128; idx += 256) {
            int sp = idx >> 7, cc = idx & 127;
            t[cc][sp] = base[sp * CC + c0 + cc];
        }
        __syncthreads();
        for (int idx = tid; idx < 128 * HW; idx += 256) {
            int cc = idx / HW, sp = idx % HW;
            int oi = (c0 + cc) * HW + sp;
            o[oi] = (t[cc][sp] - mu) * rstd * gam[oi] + bet[oi];
        }
    }
}

// ---------------- launcher ----------------------------------------------------
extern "C" void kernel_launch(void* const* d_in, const int* in_sizes, int n_in,
                              void* d_out, int out_size) {
    const float* x       = (const float*)d_in[0];
    const float* theta_w = (const float*)d_in[1];
    const float* theta_b = (const float*)d_in[2];
    const float* phi_w   = (const float*)d_in[3];
    const float* phi_b   = (const float*)d_in[4];
    const float* conv1_w = (const float*)d_in[5];
    const float* conv2_w = (const float*)d_in[6];
    const float* ln1_g   = (const float*)d_in[7];
    const float* ln1_b   = (const float*)d_in[8];
    const float* ln2_g   = (const float*)d_in[9];
    const float* ln2_b   = (const float*)d_in[10];
    float* out = (float*)d_out;

    float *xt, *phi, *F, *Mv, *xln, *r2;
    __half *xth, *wh, *thh, *pph, *xlnh, *y1h;
    cudaGetSymbolAddress((void**)&xt,   g_xt);
    cudaGetSymbolAddress((void**)&xth,  g_xth);
    cudaGetSymbolAddress((void**)&wh,   g_wh);
    cudaGetSymbolAddress((void**)&thh,  g_thh);
    cudaGetSymbolAddress((void**)&phi,  g_phi);
    cudaGetSymbolAddress((void**)&pph,  g_pph);
    cudaGetSymbolAddress((void**)&F,    g_F);
    cudaGetSymbolAddress((void**)&Mv,   g_M);
    cudaGetSymbolAddress((void**)&xln,  g_xln);
    cudaGetSymbolAddress((void**)&xlnh, g_xlnh);
    cudaGetSymbolAddress((void**)&y1h,  g_y1h);
    cudaGetSymbolAddress((void**)&r2,   g_r2);

    cudaFuncSetAttribute(tgemm_dual_kernel,
        cudaFuncAttributeMaxDynamicSharedMemorySize, DSMEM_BYTES);
    cudaFuncSetAttribute(tgemm_kernel<false, false, false, true, false>,
        cudaFuncAttributeMaxDynamicSharedMemorySize, DSMEM_BYTES);
    cudaFuncSetAttribute(tgemm_kernel<false, true, false, false, true>,
        cudaFuncAttributeMaxDynamicSharedMemorySize, DSMEM_BYTES);
    cudaFuncSetAttribute(tgemm_kernel<false, false, true, true, false>,
        cudaFuncAttributeMaxDynamicSharedMemorySize, DSMEM_BYTES);

    const int W1 = W1SZ, W2 = W2SZ;
    const int SPLIT_TOTAL = 2 * W1 + 2 * W2;

    transpose_kernel<<<dim3(NB, 4), 256>>>(x, xt, xth);
    split_all_kernel<<<SPLIT_TOTAL / 256, 256>>>(theta_w, phi_w, conv1_w, conv2_w, wh);

    // theta (half out) & phi (f32 out): [3072,512]@[256,512]^T
    tgemm_dual_kernel<<<dim3(CI_ / 64, PP / 128, 2), 128, DSMEM_BYTES>>>(
        xth, wh, wh + W1, theta_b, phi_b, thh, phi, CI_, CC);
    pool_kernel<<<dim3(NM, NB), 256>>>(phi, pph);
    // F = theta @ phip^T : [3072,256]@[768,256]^T
    tgemm_kernel<false, false, false, true, false><<<dim3(NCF / 64, PP / 128), 128, DSMEM_BYTES>>>(
        thh, pph, nullptr, nullptr, F, nullptr, NCF, CI_);
    reduceM_kernel<<<PP / 8, 256>>>(F, Mv);
    ln1_kernel<<<NB, 256>>>(xt, Mv, ln1_g, ln1_b, xln, xlnh);
    // y1 = relu(xln @ conv1_w^T) -> half
    tgemm_kernel<false, true, false, false, true><<<dim3(CC / 64, PP / 128), 128, DSMEM_BYTES>>>(
        xlnh, wh + 2 * W1, nullptr, nullptr, nullptr, y1h, CC, CC);
    // r2 = xln + y1 @ conv2_w^T -> f32
    tgemm_kernel<false, false, true, true, false><<<dim3(CC / 64, PP / 128), 128, DSMEM_BYTES>>>(
        y1h, wh + 2 * W1 + W2, nullptr, xln, r2, nullptr, CC, CC);
    ln2_kernel<<<NB, 256>>>(r2, ln2_g, ln2_b, out);
}

// round 13
// speedup vs baseline: 1.5678x; 1.1084x over previous
#include <cuda_runtime.h>
#include <cuda_fp16.h>
#include <cstdint>
#include <math.h>

// Problem constants
#define NB   64
#define CC   512
#define CI_  256
#define HH   12
#define WW   4
#define HW   48
#define PP   (NB*HW)     // 3072
#define NM   12
#define NCF  (NB*NM)     // 768
#define EPS_ 1e-5f
#define W1SZ (CI_*CC)    // 131072
#define W2SZ (CC*CC)     // 262144

// ---------------- scratch (device globals) ------------------------------------
__device__ float   g_xt  [PP * CC];
__device__ __half  g_xth [PP * CC];
__device__ __half  g_wh  [2 * W1SZ + 2 * W2SZ];   // fp16 weights (B role)
__device__ __half  g_thh [PP * CI_];
__device__ float   g_phi [PP * CI_];
__device__ __half  g_pph [NCF * CI_];
__device__ float   g_F   [PP * NCF];
__device__ float   g_M   [PP];
__device__ float   g_xln [PP * CC];
__device__ __half  g_xlnh[PP * CC];
__device__ __half  g_y1h [PP * CC];
__device__ float   g_r2  [PP * CC];

// ---------------- primitives ---------------------------------------------------
__device__ __forceinline__ uint32_t smem_u32(const void* p) {
    uint32_t a;
    asm("{ .reg .u64 t; cvta.to.shared.u64 t, %1; cvt.u32.u64 %0, t; }"
        : "=r"(a) : "l"(p));
    return a;
}
__device__ __forceinline__ void ldsm4(uint32_t* r, uint32_t addr) {
    asm volatile("ldmatrix.sync.aligned.m8n8.x4.shared.b16 {%0,%1,%2,%3}, [%4];"
                 : "=r"(r[0]), "=r"(r[1]), "=r"(r[2]), "=r"(r[3]) : "r"(addr));
}
__device__ __forceinline__ void mma_f16(float* d, const uint32_t* a, const uint32_t* b) {
    asm volatile("mma.sync.aligned.m16n8k16.row.col.f32.f16.f16.f32 "
                 "{%0,%1,%2,%3}, {%4,%5,%6,%7}, {%8,%9}, {%0,%1,%2,%3};"
                 : "+f"(d[0]), "+f"(d[1]), "+f"(d[2]), "+f"(d[3])
                 : "r"(a[0]), "r"(a[1]), "r"(a[2]), "r"(a[3]), "r"(b[0]), "r"(b[1]));
}
__device__ __forceinline__ void cp16(uint32_t s, const void* g) {
    asm volatile("cp.async.cg.shared.global [%0], [%1], 16;" :: "r"(s), "l"(g) : "memory");
}
__device__ __forceinline__ void cp_commit() {
    asm volatile("cp.async.commit_group;" ::: "memory");
}
template<int N> __device__ __forceinline__ void cp_wait() {
    asm volatile("cp.async.wait_group %0;" :: "n"(N) : "memory");
}

// smem: stage = A(8K) + B(8K) = 16K; double-buffered = 32K
#define STG_BYTES   16384
#define DSMEM_BYTES 32768

// ---------------- tensor-core GEMM, cp.async double-buffered ------------------
// C[m,n] = A[m,:]·B[n,:], pure fp16 operands.
// Tile 64x64, BK=64, 128 threads (4 warps, 2x2 grid, 32x32 per warp).
template<bool BIAS, bool RELU, bool ADD, bool EMITF, bool EMITS>
__device__ __forceinline__ void tgemm_body(
    const __half* __restrict__ Ah, const __half* __restrict__ Bh,
    const float* __restrict__ bias, const float* __restrict__ addsrc,
    float* __restrict__ outf, __half* __restrict__ oh,
    int Nc, int K, int m0, int n0, uint8_t* dsm)
{
    const int tid  = threadIdx.x;
    const int lane = tid & 31, wid = tid >> 5;
    const int wm = wid & 1, wn = wid >> 1;       // 2x2 warp grid
    const uint32_t sbase = smem_u32(dsm);

    const int rA  = (lane & 7) + ((lane >> 3) & 1) * 8;
    const int kgA = (lane >> 4) & 1;
    const int rB  = (lane & 7) + ((lane >> 4) & 1) * 8;
    const int kgB = (lane >> 3) & 1;
    const int l7  = lane & 7;

    float acc[2][4][4];                          // 32x32 per warp
    #pragma unroll
    for (int mf = 0; mf < 2; mf++)
        #pragma unroll
        for (int nf = 0; nf < 4; nf++)
            #pragma unroll
            for (int q = 0; q < 4; q++) acc[mf][nf][q] = 0.f;

    const int nch = K >> 6;

    auto stage = [&](int ch, int b) {
        const int k0 = ch << 6;
        const uint32_t abase = sbase + b * STG_BYTES;
        #pragma unroll
        for (int i = 0; i < 4; i++) {            // A: 64 rows x 8 groups
            int t = tid + i * 128;               // 0..511
            int r = t >> 3, g = t & 7;
            cp16(abase + r * 128 + ((g ^ (r & 7)) << 4),
                 Ah + (size_t)(m0 + r) * K + k0 + g * 8);
        }
        {                                        // B: 64 rows x 8 groups
            uint32_t dst = abase + 8192;
            #pragma unroll
            for (int i = 0; i < 4; i++) {
                int t = tid + i * 128;           // 0..511
                int r = t >> 3, g = t & 7;
                cp16(dst + r * 128 + ((g ^ (r & 7)) << 4),
                     Bh + (size_t)(n0 + r) * K + k0 + g * 8);
            }
        }
        cp_commit();
    };

    stage(0, 0);
    for (int ch = 0; ch < nch; ch++) {
        const int buf = ch & 1;
        if (ch + 1 < nch) { stage(ch + 1, buf ^ 1); cp_wait<1>(); }
        else              { cp_wait<0>(); }
        __syncthreads();
        const uint32_t sAu = sbase + buf * STG_BYTES;
        const uint32_t sBu = sAu + 8192;
        #pragma unroll
        for (int ks = 0; ks < 4; ks++) {
            uint32_t a[2][4], b[2][4];
            const int xA = ((ks * 2 + kgA) ^ l7) << 4;
            const int xB = ((ks * 2 + kgB) ^ l7) << 4;
            #pragma unroll
            for (int mf = 0; mf < 2; mf++) {
                int row = wm * 32 + mf * 16 + rA;
                ldsm4(a[mf], sAu + row * 128 + xA);
            }
            #pragma unroll
            for (int np = 0; np < 2; np++) {
                int row = wn * 32 + np * 16 + rB;
                ldsm4(b[np], sBu + row * 128 + xB);
            }
            #pragma unroll
            for (int mf = 0; mf < 2; mf++)
                #pragma unroll
                for (int nf = 0; nf < 4; nf++) {
                    int np = nf >> 1, sub = (nf & 1) << 1;
                    mma_f16(acc[mf][nf], a[mf], &b[np][sub]);
                }
        }
        __syncthreads();
    }
    // ---- epilogue ----
    const int mrow0 = m0 + wm * 32 + (lane >> 2);
    const int col0  = n0 + wn * 32 + (lane & 3) * 2;
    #pragma unroll
    for (int mf = 0; mf < 2; mf++)
        #pragma unroll
        for (int nf = 0; nf < 4; nf++)
            #pragma unroll
            for (int hf = 0; hf < 2; hf++) {
                int row = mrow0 + mf * 16 + hf * 8;
                int col = col0 + nf * 8;
                float vx = acc[mf][nf][hf * 2];
                float vy = acc[mf][nf][hf * 2 + 1];
                if (BIAS) { vx += bias[col]; vy += bias[col + 1]; }
                if (RELU) { vx = fmaxf(vx, 0.f); vy = fmaxf(vy, 0.f); }
                if (ADD) {
                    const float2 a2 = *(const float2*)&addsrc[(size_t)row * Nc + col];
                    vx += a2.x; vy += a2.y;
                }
                if (EMITF) *(float2*)&outf[(size_t)row * Nc + col] = make_float2(vx, vy);
                if (EMITS)
                    *(__half2*)&oh[(size_t)row * Nc + col] =
                        __halves2half2(__float2half_rn(vx), __float2half_rn(vy));
            }
}

template<bool BIAS, bool RELU, bool ADD, bool EMITF, bool EMITS>
__global__ __launch_bounds__(128) void tgemm_kernel(
    const __half* __restrict__ Ah, const __half* __restrict__ Bh,
    const float* __restrict__ bias, const float* __restrict__ addsrc,
    float* __restrict__ outf, __half* __restrict__ oh,
    int Nc, int K)
{
    extern __shared__ uint8_t dsm[];
    tgemm_body<BIAS, RELU, ADD, EMITF, EMITS>(Ah, Bh, bias, addsrc,
        outf, oh, Nc, K, blockIdx.y * 64, blockIdx.x * 64, dsm);
}

// dual projection: z=0 -> theta (half out), z=1 -> phi (f32 out)
__global__ __launch_bounds__(128) void tgemm_dual_kernel(
    const __half* __restrict__ Ah,
    const __half* __restrict__ B0h, const __half* __restrict__ B1h,
    const float* __restrict__ bias0, const float* __restrict__ bias1,
    __half* __restrict__ thh, float* __restrict__ phi, int Nc, int K)
{
    extern __shared__ uint8_t dsm[];
    if (blockIdx.z == 0)
        tgemm_body<true, false, false, false, true>(Ah, B0h, bias0, nullptr,
            nullptr, thh, Nc, K, blockIdx.y * 64, blockIdx.x * 64, dsm);
    else
        tgemm_body<true, false, false, true, false>(Ah, B1h, bias1, nullptr,
            phi, nullptr, Nc, K, blockIdx.y * 64, blockIdx.x * 64, dsm);
}

// ---------------- prep: transpose x AND cast all weights (one launch) ---------
__global__ __launch_bounds__(256) void prep_kernel(const float* __restrict__ x,
                                                   float* __restrict__ xt,
                                                   __half* __restrict__ xh,
                                                   const float* __restrict__ w0,
                                                   const float* __restrict__ w1,
                                                   const float* __restrict__ w2,
                                                   const float* __restrict__ w3,
                                                   __half* __restrict__ wh) {
    int tid = threadIdx.x;
    if (blockIdx.x < 256) {
        int j  = blockIdx.x >> 2;
        int c0 = (blockIdx.x & 3) * 128;
        __shared__ float t[128][49];
        const float* xb = x + j * (CC * HW);
        for (int idx = tid; idx < 128 * HW; idx += 256) {
            int cc = idx / HW, s = idx % HW;
            t[cc][s] = xb[(c0 + cc) * HW + s];
        }
        __syncthreads();
        size_t ob = (size_t)j * HW * CC;
        for (int idx = tid; idx < HW * 128; idx += 256) {
            int s = idx >> 7, cc = idx & 127;
            float v = t[cc][s];
            size_t o = ob + s * CC + c0 + cc;
            xt[o] = v;
            xh[o] = __float2half_rn(v);
        }
    } else {
        int i = (blockIdx.x - 256) * 256 + tid;   // < 2*W1SZ + 2*W2SZ
        const float* src; int off;
        if (i < W1SZ)                  { src = w0; off = i; }
        else if (i < 2 * W1SZ)         { src = w1; off = i - W1SZ; }
        else if (i < 2 * W1SZ + W2SZ)  { src = w2; off = i - 2 * W1SZ; }
        else                           { src = w3; off = i - 2 * W1SZ - W2SZ; }
        wh[i] = __float2half_rn(src[off]);
    }
}

// ---------------- maxpool 2x2 on phi -> phip (fp16) ---------------------------
__global__ __launch_bounds__(256) void pool_kernel(const float* __restrict__ phi,
                                                   __half* __restrict__ ph) {
    int m = blockIdx.x, i = blockIdx.y;
    int c = threadIdx.x;   // 256 = CI
    int phh = m >> 1, pw = m & 1;
    int s0 = (2 * phh) * WW + 2 * pw;
    const float* b = phi + (size_t)(i * HW) * CI_ + c;
    float v = b[(size_t)s0 * CI_];
    v = fmaxf(v, b[(size_t)(s0 + 1) * CI_]);
    v = fmaxf(v, b[(size_t)(s0 + WW) * CI_]);
    v = fmaxf(v, b[(size_t)(s0 + WW + 1) * CI_]);
    ph[(size_t)(i * NM + m) * CI_ + c] = __float2half_rn(v);
}

// ---------------- reduce F -> M (float4-vectorized group max) -----------------
__global__ __launch_bounds__(256) void reduceM_kernel(const float* __restrict__ F,
                                                      float* __restrict__ Mv) {
    int p = blockIdx.x * 8 + (threadIdx.x >> 5);
    int lane = threadIdx.x & 31;
    const float4* row4 = (const float4*)(F + (size_t)p * NCF);  // 192 float4s
    float s = 0.f;
    #pragma unroll
    for (int g = lane; g < NB; g += 32) {
        float4 a = row4[3 * g], b = row4[3 * g + 1], c = row4[3 * g + 2];
        float v = fmaxf(fmaxf(fmaxf(a.x, a.y), fmaxf(a.z, a.w)),
                  fmaxf(fmaxf(fmaxf(b.x, b.y), fmaxf(b.z, b.w)),
                        fmaxf(fmaxf(c.x, c.y), fmaxf(c.z, c.w))));
        s += v;
    }
    #pragma unroll
    for (int o = 16; o > 0; o >>= 1) s += __shfl_down_sync(0xffffffffu, s, o);
    if (lane == 0) Mv[p] = s * (1.0f / 12.0f);
}

// ---------------- block reduction helper --------------------------------------
__device__ __forceinline__ float blockReduceSum256(float v, float* sbuf) {
    #pragma unroll
    for (int o = 16; o > 0; o >>= 1) v += __shfl_down_sync(0xffffffffu, v, o);
    int lane = threadIdx.x & 31, w = threadIdx.x >> 5;
    if (lane == 0) sbuf[w] = v;
    __syncthreads();
    v = (threadIdx.x < 8) ? sbuf[threadIdx.x] : 0.f;
    if (w == 0) {
        #pragma unroll
        for (int o = 4; o > 0; o >>= 1) v += __shfl_down_sync(0xffu, v, o);
    }
    return v;
}

// ---------------- res1 + LN1 (emits f32 + fp16) -------------------------------
__global__ __launch_bounds__(256) void ln1_kernel(const float* __restrict__ xt,
                                                  const float* __restrict__ Mv,
                                                  const float* __restrict__ gam,
                                                  const float* __restrict__ bet,
                                                  float* __restrict__ xln,
                                                  __half* __restrict__ xh) {
    int j = blockIdx.x, tid = threadIdx.x;
    __shared__ float sbuf[32];
    __shared__ float s_mu, s_rstd;
    __shared__ float s_scale[HW];
    if (tid < HW) s_scale[tid] = 1.0f + Mv[j * HW + tid];
    __syncthreads();
    const float* base = xt + (size_t)j * (HW * CC);
    float sum = 0.f, sq = 0.f;
    for (int idx = tid; idx < HW * CC; idx += 256) {
        float v = base[idx] * s_scale[idx >> 9];
        sum += v; sq += v * v;
    }
    float ts = blockReduceSum256(sum, sbuf);
    __syncthreads();
    float tq = blockReduceSum256(sq, sbuf);
    if (tid == 0) {
        float mu = ts * (1.0f / (HW * CC));
        float var = tq * (1.0f / (HW * CC)) - mu * mu;
        s_mu = mu; s_rstd = rsqrtf(var + EPS_);
    }
    __syncthreads();
    float mu = s_mu, rstd = s_rstd;
    size_t ob = (size_t)j * (HW * CC);
    for (int idx = tid; idx < HW * CC; idx += 256) {
        int s = idx >> 9, c = idx & 511;
        float v = base[idx] * s_scale[s];
        float r = (v - mu) * rstd * gam[c * HW + s] + bet[c * HW + s];
        xln[ob + idx] = r;
        xh[ob + idx] = __float2half_rn(r);
    }
}

// ---------------- LN2 + output in NCHW (smem-transposed, fully coalesced) -----
__global__ __launch_bounds__(256) void ln2_kernel(const float* __restrict__ r2,
                                                  const float* __restrict__ gam,
                                                  const float* __restrict__ bet,
                                                  float* __restrict__ out) {
    int j = blockIdx.x, tid = threadIdx.x;
    __shared__ float sbuf[32];
    __shared__ float s_mu, s_rstd;
    __shared__ float t[128][49];
    const float* base = r2 + (size_t)j * (HW * CC);
    float sum = 0.f, sq = 0.f;
    for (int idx = tid; idx < HW * CC; idx += 256) {
        float v = base[idx];
        sum += v; sq += v * v;
    }
    float ts = blockReduceSum256(sum, sbuf);
    __syncthreads();
    float tq = blockReduceSum256(sq, sbuf);
    if (tid == 0) {
        float mu = ts * (1.0f / (HW * CC));
        float var = tq * (1.0f / (HW * CC)) - mu * mu;
        s_mu = mu; s_rstd = rsqrtf(var + EPS_);
    }
    __syncthreads();
    float mu = s_mu, rstd = s_rstd;
    float* o = out + (size_t)j * (HW * CC);
    for (int c0 = 0; c0 < CC; c0 += 128) {
        __syncthreads();
        for (int idx = tid; idx < HW * 128; idx += 256) {
            int sp = idx >> 7, cc = idx & 127;
            t[cc][sp] = base[sp * CC + c0 + cc];
        }
        __syncthreads();
        for (int idx = tid; idx < 128 * HW; idx += 256) {
            int cc = idx / HW, sp = idx % HW;
            int oi = (c0 + cc) * HW + sp;
            o[oi] = (t[cc][sp] - mu) * rstd * gam[oi] + bet[oi];
        }
    }
}

// ---------------- launcher ----------------------------------------------------
extern "C" void kernel_launch(void* const* d_in, const int* in_sizes, int n_in,
                              void* d_out, int out_size) {
    const float* x       = (const float*)d_in[0];
    const float* theta_w = (const float*)d_in[1];
    const float* theta_b = (const float*)d_in[2];
    const float* phi_w   = (const float*)d_in[3];
    const float* phi_b   = (const float*)d_in[4];
    const float* conv1_w = (const float*)d_in[5];
    const float* conv2_w = (const float*)d_in[6];
    const float* ln1_g   = (const float*)d_in[7];
    const float* ln1_b   = (const float*)d_in[8];
    const float* ln2_g   = (const float*)d_in[9];
    const float* ln2_b   = (const float*)d_in[10];
    float* out = (float*)d_out;

    float *xt, *phi, *F, *Mv, *xln, *r2;
    __half *xth, *wh, *thh, *pph, *xlnh, *y1h;
    cudaGetSymbolAddress((void**)&xt,   g_xt);
    cudaGetSymbolAddress((void**)&xth,  g_xth);
    cudaGetSymbolAddress((void**)&wh,   g_wh);
    cudaGetSymbolAddress((void**)&thh,  g_thh);
    cudaGetSymbolAddress((void**)&phi,  g_phi);
    cudaGetSymbolAddress((void**)&pph,  g_pph);
    cudaGetSymbolAddress((void**)&F,    g_F);
    cudaGetSymbolAddress((void**)&Mv,   g_M);
    cudaGetSymbolAddress((void**)&xln,  g_xln);
    cudaGetSymbolAddress((void**)&xlnh, g_xlnh);
    cudaGetSymbolAddress((void**)&y1h,  g_y1h);
    cudaGetSymbolAddress((void**)&r2,   g_r2);

    cudaFuncSetAttribute(tgemm_dual_kernel,
        cudaFuncAttributeMaxDynamicSharedMemorySize, DSMEM_BYTES);
    cudaFuncSetAttribute(tgemm_kernel<false, false, false, true, false>,
        cudaFuncAttributeMaxDynamicSharedMemorySize, DSMEM_BYTES);
    cudaFuncSetAttribute(tgemm_kernel<false, true, false, false, true>,
        cudaFuncAttributeMaxDynamicSharedMemorySize, DSMEM_BYTES);
    cudaFuncSetAttribute(tgemm_kernel<false, false, true, true, false>,
        cudaFuncAttributeMaxDynamicSharedMemorySize, DSMEM_BYTES);

    const int W1 = W1SZ, W2 = W2SZ;
    const int SPLIT_BLOCKS = (2 * W1 + 2 * W2) / 256;   // 3072

    // transpose x + cast all weights in one launch
    prep_kernel<<<256 + SPLIT_BLOCKS, 256>>>(x, xt, xth,
        theta_w, phi_w, conv1_w, conv2_w, wh);

    // theta (half out) & phi (f32 out): [3072,512]@[256,512]^T
    tgemm_dual_kernel<<<dim3(CI_ / 64, PP / 64, 2), 128, DSMEM_BYTES>>>(
        xth, wh, wh + W1, theta_b, phi_b, thh, phi, CI_, CC);
    pool_kernel<<<dim3(NM, NB), 256>>>(phi, pph);
    // F = theta @ phip^T : [3072,256]@[768,256]^T
    tgemm_kernel<false, false, false, true, false><<<dim3(NCF / 64, PP / 64), 128, DSMEM_BYTES>>>(
        thh, pph, nullptr, nullptr, F, nullptr, NCF, CI_);
    reduceM_kernel<<<PP / 8, 256>>>(F, Mv);
    ln1_kernel<<<NB, 256>>>(xt, Mv, ln1_g, ln1_b, xln, xlnh);
    // y1 = relu(xln @ conv1_w^T) -> half
    tgemm_kernel<false, true, false, false, true><<<dim3(CC / 64, PP / 64), 128, DSMEM_BYTES>>>(
        xlnh, wh + 2 * W1, nullptr, nullptr, nullptr, y1h, CC, CC);
    // r2 = xln + y1 @ conv2_w^T -> f32
    tgemm_kernel<false, false, true, true, false><<<dim3(CC / 64, PP / 64), 128, DSMEM_BYTES>>>(
        y1h, wh + 2 * W1 + W2, nullptr, xln, r2, nullptr, CC, CC);
    ln2_kernel<<<NB, 256>>>(r2, ln2_g, ln2_b, out);
}

// round 14
// speedup vs baseline: 1.7189x; 1.0964x over previous
#include <cuda_runtime.h>
#include <cuda_fp16.h>
#include <cstdint>
#include <math.h>

// Problem constants
#define NB   64
#define CC   512
#define CI_  256
#define HH   12
#define WW   4
#define HW   48
#define PP   (NB*HW)     // 3072
#define NM   12
#define NCF  (NB*NM)     // 768
#define EPS_ 1e-5f
#define W1SZ (CI_*CC)    // 131072
#define W2SZ (CC*CC)     // 262144

// ---------------- scratch (device globals) ------------------------------------
__device__ float   g_xt  [PP * CC];
__device__ __half  g_xth [PP * CC];
__device__ __half  g_wh  [2 * W1SZ + 2 * W2SZ];   // fp16 weights (B role)
__device__ __half  g_thh [PP * CI_];
__device__ __half  g_phih[PP * CI_];
__device__ __half  g_pph [NCF * CI_];
__device__ __half  g_Fh  [PP * NCF];
__device__ float   g_M   [PP];
__device__ float   g_xln [PP * CC];
__device__ __half  g_xlnh[PP * CC];
__device__ __half  g_y1h [PP * CC];
__device__ float   g_r2  [PP * CC];

// ---------------- primitives ---------------------------------------------------
__device__ __forceinline__ uint32_t smem_u32(const void* p) {
    uint32_t a;
    asm("{ .reg .u64 t; cvta.to.shared.u64 t, %1; cvt.u32.u64 %0, t; }"
        : "=r"(a) : "l"(p));
    return a;
}
__device__ __forceinline__ void ldsm4(uint32_t* r, uint32_t addr) {
    asm volatile("ldmatrix.sync.aligned.m8n8.x4.shared.b16 {%0,%1,%2,%3}, [%4];"
                 : "=r"(r[0]), "=r"(r[1]), "=r"(r[2]), "=r"(r[3]) : "r"(addr));
}
__device__ __forceinline__ void mma_f16(float* d, const uint32_t* a, const uint32_t* b) {
    asm volatile("mma.sync.aligned.m16n8k16.row.col.f32.f16.f16.f32 "
                 "{%0,%1,%2,%3}, {%4,%5,%6,%7}, {%8,%9}, {%0,%1,%2,%3};"
                 : "+f"(d[0]), "+f"(d[1]), "+f"(d[2]), "+f"(d[3])
                 : "r"(a[0]), "r"(a[1]), "r"(a[2]), "r"(a[3]), "r"(b[0]), "r"(b[1]));
}
__device__ __forceinline__ void cp16(uint32_t s, const void* g) {
    asm volatile("cp.async.cg.shared.global [%0], [%1], 16;" :: "r"(s), "l"(g) : "memory");
}
__device__ __forceinline__ void cp_commit() {
    asm volatile("cp.async.commit_group;" ::: "memory");
}
template<int N> __device__ __forceinline__ void cp_wait() {
    asm volatile("cp.async.wait_group %0;" :: "n"(N) : "memory");
}

// smem: stage = A(8K) + B(8K) = 16K; double-buffered = 32K
#define STG_BYTES   16384
#define DSMEM_BYTES 32768
// LN kernels: per-sample slab with stride-513 padding: 48 * 513 * 4 = 98496 B
#define LN_STRIDE   513
#define LN_SMEM     (HW * LN_STRIDE * 4)

// ---------------- tensor-core GEMM, cp.async double-buffered ------------------
// C[m,n] = A[m,:]·B[n,:], pure fp16 operands.
// Tile 64x64, BK=64, 128 threads (4 warps, 2x2 grid, 32x32 per warp).
template<bool BIAS, bool RELU, bool ADD, bool EMITF, bool EMITS>
__device__ __forceinline__ void tgemm_body(
    const __half* __restrict__ Ah, const __half* __restrict__ Bh,
    const float* __restrict__ bias, const float* __restrict__ addsrc,
    float* __restrict__ outf, __half* __restrict__ oh,
    int Nc, int K, int m0, int n0, uint8_t* dsm)
{
    const int tid  = threadIdx.x;
    const int lane = tid & 31, wid = tid >> 5;
    const int wm = wid & 1, wn = wid >> 1;       // 2x2 warp grid
    const uint32_t sbase = smem_u32(dsm);

    const int rA  = (lane & 7) + ((lane >> 3) & 1) * 8;
    const int kgA = (lane >> 4) & 1;
    const int rB  = (lane & 7) + ((lane >> 4) & 1) * 8;
    const int kgB = (lane >> 3) & 1;
    const int l7  = lane & 7;

    float acc[2][4][4];                          // 32x32 per warp
    #pragma unroll
    for (int mf = 0; mf < 2; mf++)
        #pragma unroll
        for (int nf = 0; nf < 4; nf++)
            #pragma unroll
            for (int q = 0; q < 4; q++) acc[mf][nf][q] = 0.f;

    const int nch = K >> 6;

    auto stage = [&](int ch, int b) {
        const int k0 = ch << 6;
        const uint32_t abase = sbase + b * STG_BYTES;
        #pragma unroll
        for (int i = 0; i < 4; i++) {            // A: 64 rows x 8 groups
            int t = tid + i * 128;               // 0..511
            int r = t >> 3, g = t & 7;
            cp16(abase + r * 128 + ((g ^ (r & 7)) << 4),
                 Ah + (size_t)(m0 + r) * K + k0 + g * 8);
        }
        {                                        // B: 64 rows x 8 groups
            uint32_t dst = abase + 8192;
            #pragma unroll
            for (int i = 0; i < 4; i++) {
                int t = tid + i * 128;           // 0..511
                int r = t >> 3, g = t & 7;
                cp16(dst + r * 128 + ((g ^ (r & 7)) << 4),
                     Bh + (size_t)(n0 + r) * K + k0 + g * 8);
            }
        }
        cp_commit();
    };

    stage(0, 0);
    for (int ch = 0; ch < nch; ch++) {
        const int buf = ch & 1;
        if (ch + 1 < nch) { stage(ch + 1, buf ^ 1); cp_wait<1>(); }
        else              { cp_wait<0>(); }
        __syncthreads();
        const uint32_t sAu = sbase + buf * STG_BYTES;
        const uint32_t sBu = sAu + 8192;
        #pragma unroll
        for (int ks = 0; ks < 4; ks++) {
            uint32_t a[2][4], b[2][4];
            const int xA = ((ks * 2 + kgA) ^ l7) << 4;
            const int xB = ((ks * 2 + kgB) ^ l7) << 4;
            #pragma unroll
            for (int mf = 0; mf < 2; mf++) {
                int row = wm * 32 + mf * 16 + rA;
                ldsm4(a[mf], sAu + row * 128 + xA);
            }
            #pragma unroll
            for (int np = 0; np < 2; np++) {
                int row = wn * 32 + np * 16 + rB;
                ldsm4(b[np], sBu + row * 128 + xB);
            }
            #pragma unroll
            for (int mf = 0; mf < 2; mf++)
                #pragma unroll
                for (int nf = 0; nf < 4; nf++) {
                    int np = nf >> 1, sub = (nf & 1) << 1;
                    mma_f16(acc[mf][nf], a[mf], &b[np][sub]);
                }
        }
        __syncthreads();
    }
    // ---- epilogue ----
    const int mrow0 = m0 + wm * 32 + (lane >> 2);
    const int col0  = n0 + wn * 32 + (lane & 3) * 2;
    #pragma unroll
    for (int mf = 0; mf < 2; mf++)
        #pragma unroll
        for (int nf = 0; nf < 4; nf++)
            #pragma unroll
            for (int hf = 0; hf < 2; hf++) {
                int row = mrow0 + mf * 16 + hf * 8;
                int col = col0 + nf * 8;
                float vx = acc[mf][nf][hf * 2];
                float vy = acc[mf][nf][hf * 2 + 1];
                if (BIAS) { vx += bias[col]; vy += bias[col + 1]; }
                if (RELU) { vx = fmaxf(vx, 0.f); vy = fmaxf(vy, 0.f); }
                if (ADD) {
                    const float2 a2 = *(const float2*)&addsrc[(size_t)row * Nc + col];
                    vx += a2.x; vy += a2.y;
                }
                if (EMITF) *(float2*)&outf[(size_t)row * Nc + col] = make_float2(vx, vy);
                if (EMITS)
                    *(__half2*)&oh[(size_t)row * Nc + col] =
                        __halves2half2(__float2half_rn(vx), __float2half_rn(vy));
            }
}

template<bool BIAS, bool RELU, bool ADD, bool EMITF, bool EMITS>
__global__ __launch_bounds__(128) void tgemm_kernel(
    const __half* __restrict__ Ah, const __half* __restrict__ Bh,
    const float* __restrict__ bias, const float* __restrict__ addsrc,
    float* __restrict__ outf, __half* __restrict__ oh,
    int Nc, int K)
{
    extern __shared__ uint8_t dsm[];
    tgemm_body<BIAS, RELU, ADD, EMITF, EMITS>(Ah, Bh, bias, addsrc,
        outf, oh, Nc, K, blockIdx.y * 64, blockIdx.x * 64, dsm);
}

// dual projection: z=0 -> theta, z=1 -> phi (both fp16 out)
__global__ __launch_bounds__(128) void tgemm_dual_kernel(
    const __half* __restrict__ Ah,
    const __half* __restrict__ B0h, const __half* __restrict__ B1h,
    const float* __restrict__ bias0, const float* __restrict__ bias1,
    __half* __restrict__ thh, __half* __restrict__ phih, int Nc, int K)
{
    extern __shared__ uint8_t dsm[];
    bool z = blockIdx.z != 0;
    tgemm_body<true, false, false, false, true>(Ah, z ? B1h : B0h,
        z ? bias1 : bias0, nullptr, nullptr, z ? phih : thh,
        Nc, K, blockIdx.y * 64, blockIdx.x * 64, dsm);
}

// ---------------- prep: transpose x AND cast all weights (one launch) ---------
__global__ __launch_bounds__(256) void prep_kernel(const float* __restrict__ x,
                                                   float* __restrict__ xt,
                                                   __half* __restrict__ xh,
                                                   const float* __restrict__ w0,
                                                   const float* __restrict__ w1,
                                                   const float* __restrict__ w2,
                                                   const float* __restrict__ w3,
                                                   __half* __restrict__ wh) {
    int tid = threadIdx.x;
    if (blockIdx.x < 256) {
        int j  = blockIdx.x >> 2;
        int c0 = (blockIdx.x & 3) * 128;
        __shared__ float t[128][49];
        const float* xb = x + j * (CC * HW);
        for (int idx = tid; idx < 128 * HW; idx += 256) {
            int cc = idx / HW, s = idx % HW;
            t[cc][s] = xb[(c0 + cc) * HW + s];
        }
        __syncthreads();
        size_t ob = (size_t)j * HW * CC;
        for (int idx = tid; idx < HW * 128; idx += 256) {
            int s = idx >> 7, cc = idx & 127;
            float v = t[cc][s];
            size_t o = ob + s * CC + c0 + cc;
            xt[o] = v;
            xh[o] = __float2half_rn(v);
        }
    } else {
        int i = (blockIdx.x - 256) * 256 + tid;   // < 2*W1SZ + 2*W2SZ
        const float* src; int off;
        if (i < W1SZ)                  { src = w0; off = i; }
        else if (i < 2 * W1SZ)         { src = w1; off = i - W1SZ; }
        else if (i < 2 * W1SZ + W2SZ)  { src = w2; off = i - 2 * W1SZ; }
        else                           { src = w3; off = i - 2 * W1SZ - W2SZ; }
        wh[i] = __float2half_rn(src[off]);
    }
}

// ---------------- maxpool 2x2 on phi (fp16 in/out) ----------------------------
__global__ __launch_bounds__(256) void pool_kernel(const __half* __restrict__ phi,
                                                   __half* __restrict__ ph) {
    int m = blockIdx.x, i = blockIdx.y;
    int c = threadIdx.x;   // 256 = CI
    int phh = m >> 1, pw = m & 1;
    int s0 = (2 * phh) * WW + 2 * pw;
    const __half* b = phi + (size_t)(i * HW) * CI_ + c;
    float v = __half2float(b[(size_t)s0 * CI_]);
    v = fmaxf(v, __half2float(b[(size_t)(s0 + 1) * CI_]));
    v = fmaxf(v, __half2float(b[(size_t)(s0 + WW) * CI_]));
    v = fmaxf(v, __half2float(b[(size_t)(s0 + WW + 1) * CI_]));
    ph[(size_t)(i * NM + m) * CI_ + c] = __float2half_rn(v);
}

// ---------------- reduce F(half) -> M -----------------------------------------
__global__ __launch_bounds__(256) void reduceM_kernel(const __half* __restrict__ F,
                                                      float* __restrict__ Mv) {
    int p = blockIdx.x * 8 + (threadIdx.x >> 5);
    int lane = threadIdx.x & 31;
    const __half* row = F + (size_t)p * NCF;
    float s = 0.f;
    #pragma unroll
    for (int g = lane; g < NB; g += 32) {
        // group g = 12 halves = 24 bytes, 8B-aligned -> 3 x uint2
        const uint2* q = (const uint2*)(row + 12 * g);
        uint2 u0 = q[0], u1 = q[1], u2 = q[2];
        __half2 h0 = *(__half2*)&u0.x, h1 = *(__half2*)&u0.y;
        __half2 h2 = *(__half2*)&u1.x, h3 = *(__half2*)&u1.y;
        __half2 h4 = *(__half2*)&u2.x, h5 = *(__half2*)&u2.y;
        __half2 m2 = __hmax2(__hmax2(h0, h1), __hmax2(__hmax2(h2, h3), __hmax2(h4, h5)));
        s += fmaxf(__half2float(__low2half(m2)), __half2float(__high2half(m2)));
    }
    #pragma unroll
    for (int o = 16; o > 0; o >>= 1) s += __shfl_down_sync(0xffffffffu, s, o);
    if (lane == 0) Mv[p] = s * (1.0f / 12.0f);
}

// ---------------- block reduction (16 warps) ----------------------------------
__device__ __forceinline__ float blockReduceSum512(float v, float* sbuf) {
    #pragma unroll
    for (int o = 16; o > 0; o >>= 1) v += __shfl_down_sync(0xffffffffu, v, o);
    int lane = threadIdx.x & 31, w = threadIdx.x >> 5;
    if (lane == 0) sbuf[w] = v;
    __syncthreads();
    v = (threadIdx.x < 16) ? sbuf[threadIdx.x] : 0.f;
    if (w == 0) {
        #pragma unroll
        for (int o = 8; o > 0; o >>= 1) v += __shfl_down_sync(0xffffffffu, v, o);
    }
    return v;
}

// ---------------- res1 + LN1 (smem-cached sample, emits f32 + fp16) -----------
__global__ __launch_bounds__(512) void ln1_kernel(const float* __restrict__ xt,
                                                  const float* __restrict__ Mv,
                                                  const float* __restrict__ gam,
                                                  const float* __restrict__ bet,
                                                  float* __restrict__ xln,
                                                  __half* __restrict__ xh) {
    extern __shared__ float slab[];   // [HW][LN_STRIDE]
    int j = blockIdx.x, tid = threadIdx.x;
    __shared__ float sbuf[16];
    __shared__ float s_mu, s_rstd;
    __shared__ float s_scale[HW];
    if (tid < HW) s_scale[tid] = 1.0f + Mv[j * HW + tid];
    __syncthreads();
    const float* base = xt + (size_t)j * (HW * CC);
    float sum = 0.f, sq = 0.f;
    for (int idx = tid; idx < HW * CC; idx += 512) {
        int s = idx >> 9, c = idx & 511;
        float v = base[idx] * s_scale[s];
        slab[s * LN_STRIDE + c] = v;
        sum += v; sq += v * v;
    }
    float ts = blockReduceSum512(sum, sbuf);
    __syncthreads();
    float tq = blockReduceSum512(sq, sbuf);
    if (tid == 0) {
        float mu = ts * (1.0f / (HW * CC));
        float var = tq * (1.0f / (HW * CC)) - mu * mu;
        s_mu = mu; s_rstd = rsqrtf(var + EPS_);
    }
    __syncthreads();
    float mu = s_mu, rstd = s_rstd;
    size_t ob = (size_t)j * (HW * CC);
    for (int idx = tid; idx < HW * CC; idx += 512) {
        int s = idx >> 9, c = idx & 511;
        float v = slab[s * LN_STRIDE + c];
        float r = (v - mu) * rstd * gam[c * HW + s] + bet[c * HW + s];
        xln[ob + idx] = r;
        xh[ob + idx] = __float2half_rn(r);
    }
}

// ---------------- LN2 + NCHW output (smem-cached sample) ----------------------
__global__ __launch_bounds__(512) void ln2_kernel(const float* __restrict__ r2,
                                                  const float* __restrict__ gam,
                                                  const float* __restrict__ bet,
                                                  float* __restrict__ out) {
    extern __shared__ float slab[];   // [HW][LN_STRIDE]
    int j = blockIdx.x, tid = threadIdx.x;
    __shared__ float sbuf[16];
    __shared__ float s_mu, s_rstd;
    const float* base = r2 + (size_t)j * (HW * CC);
    float sum = 0.f, sq = 0.f;
    for (int idx = tid; idx < HW * CC; idx += 512) {
        int s = idx >> 9, c = idx & 511;
        float v = base[idx];
        slab[s * LN_STRIDE + c] = v;
        sum += v; sq += v * v;
    }
    float ts = blockReduceSum512(sum, sbuf);
    __syncthreads();
    float tq = blockReduceSum512(sq, sbuf);
    if (tid == 0) {
        float mu = ts * (1.0f / (HW * CC));
        float var = tq * (1.0f / (HW * CC)) - mu * mu;
        s_mu = mu; s_rstd = rsqrtf(var + EPS_);
    }
    __syncthreads();
    float mu = s_mu, rstd = s_rstd;
    float* o = out + (size_t)j * (HW * CC);
    // output idx = c*48 + sp : consecutive tid -> consecutive sp, smem bank-safe
    for (int idx = tid; idx < HW * CC; idx += 512) {
        int c = idx / HW, sp = idx % HW;
        float v = slab[sp * LN_STRIDE + c];
        o[idx] = (v - mu) * rstd * gam[idx] + bet[idx];
    }
}

// ---------------- launcher ----------------------------------------------------
extern "C" void kernel_launch(void* const* d_in, const int* in_sizes, int n_in,
                              void* d_out, int out_size) {
    const float* x       = (const float*)d_in[0];
    const float* theta_w = (const float*)d_in[1];
    const float* theta_b = (const float*)d_in[2];
    const float* phi_w   = (const float*)d_in[3];
    const float* phi_b   = (const float*)d_in[4];
    const float* conv1_w = (const float*)d_in[5];
    const float* conv2_w = (const float*)d_in[6];
    const float* ln1_g   = (const float*)d_in[7];
    const float* ln1_b   = (const float*)d_in[8];
    const float* ln2_g   = (const float*)d_in[9];
    const float* ln2_b   = (const float*)d_in[10];
    float* out = (float*)d_out;

    float *xt, *Mv, *xln, *r2;
    __half *xth, *wh, *thh, *phih, *pph, *Fh, *xlnh, *y1h;
    cudaGetSymbolAddress((void**)&xt,   g_xt);
    cudaGetSymbolAddress((void**)&xth,  g_xth);
    cudaGetSymbolAddress((void**)&wh,   g_wh);
    cudaGetSymbolAddress((void**)&thh,  g_thh);
    cudaGetSymbolAddress((void**)&phih, g_phih);
    cudaGetSymbolAddress((void**)&pph,  g_pph);
    cudaGetSymbolAddress((void**)&Fh,   g_Fh);
    cudaGetSymbolAddress((void**)&Mv,   g_M);
    cudaGetSymbolAddress((void**)&xln,  g_xln);
    cudaGetSymbolAddress((void**)&xlnh, g_xlnh);
    cudaGetSymbolAddress((void**)&y1h,  g_y1h);
    cudaGetSymbolAddress((void**)&r2,   g_r2);

    cudaFuncSetAttribute(tgemm_dual_kernel,
        cudaFuncAttributeMaxDynamicSharedMemorySize, DSMEM_BYTES);
    cudaFuncSetAttribute(tgemm_kernel<false, false, false, false, true>,
        cudaFuncAttributeMaxDynamicSharedMemorySize, DSMEM_BYTES);
    cudaFuncSetAttribute(tgemm_kernel<false, true, false, false, true>,
        cudaFuncAttributeMaxDynamicSharedMemorySize, DSMEM_BYTES);
    cudaFuncSetAttribute(tgemm_kernel<false, false, true, true, false>,
        cudaFuncAttributeMaxDynamicSharedMemorySize, DSMEM_BYTES);
    cudaFuncSetAttribute(ln1_kernel,
        cudaFuncAttributeMaxDynamicSharedMemorySize, LN_SMEM);
    cudaFuncSetAttribute(ln2_kernel,
        cudaFuncAttributeMaxDynamicSharedMemorySize, LN_SMEM);

    const int W1 = W1SZ, W2 = W2SZ;
    const int SPLIT_BLOCKS = (2 * W1 + 2 * W2) / 256;   // 3072

    // transpose x + cast all weights in one launch
    prep_kernel<<<256 + SPLIT_BLOCKS, 256>>>(x, xt, xth,
        theta_w, phi_w, conv1_w, conv2_w, wh);

    // theta & phi (both fp16 out): [3072,512]@[256,512]^T
    tgemm_dual_kernel<<<dim3(CI_ / 64, PP / 64, 2), 128, DSMEM_BYTES>>>(
        xth, wh, wh + W1, theta_b, phi_b, thh, phih, CI_, CC);
    pool_kernel<<<dim3(NM, NB), 256>>>(phih, pph);
    // F = theta @ phip^T (fp16 out): [3072,256]@[768,256]^T
    tgemm_kernel<false, false, false, false, true><<<dim3(NCF / 64, PP / 64), 128, DSMEM_BYTES>>>(
        thh, pph, nullptr, nullptr, nullptr, Fh, NCF, CI_);
    reduceM_kernel<<<PP / 8, 256>>>(Fh, Mv);
    ln1_kernel<<<NB, 512, LN_SMEM>>>(xt, Mv, ln1_g, ln1_b, xln, xlnh);
    // y1 = relu(xln @ conv1_w^T) -> half
    tgemm_kernel<false, true, false, false, true><<<dim3(CC / 64, PP / 64), 128, DSMEM_BYTES>>>(
        xlnh, wh + 2 * W1, nullptr, nullptr, nullptr, y1h, CC, CC);
    // r2 = xln + y1 @ conv2_w^T -> f32
    tgemm_kernel<false, false, true, true, false><<<dim3(CC / 64, PP / 64), 128, DSMEM_BYTES>>>(
        y1h, wh + 2 * W1 + W2, nullptr, xln, r2, nullptr, CC, CC);
    ln2_kernel<<<NB, 512, LN_SMEM>>>(r2, ln2_g, ln2_b, out);
}

// round 16
// speedup vs baseline: 1.7675x; 1.0283x over previous
#include <cuda_runtime.h>
#include <cuda_fp16.h>
#include <cstdint>
#include <math.h>

// Problem constants
#define NB   64
#define CC   512
#define CI_  256
#define HH   12
#define WW   4
#define HW   48
#define PP   (NB*HW)     // 3072
#define NM   12
#define NCF  (NB*NM)     // 768
#define EPS_ 1e-5f
#define W1SZ (CI_*CC)    // 131072
#define W2SZ (CC*CC)     // 262144

// ---------------- scratch (device globals) ------------------------------------
__device__ __half  g_xth [PP * CC];
__device__ __half  g_wh  [2 * W1SZ + 2 * W2SZ];   // fp16 weights (B role)
__device__ __half  g_thh [PP * CI_];
__device__ __half  g_phih[PP * CI_];
__device__ __half  g_pph [NCF * CI_];
__device__ __half  g_Fh  [PP * NCF];
__device__ float   g_M   [PP];
__device__ float   g_xln [PP * CC];
__device__ __half  g_xlnh[PP * CC];
__device__ __half  g_y1h [PP * CC];
__device__ float   g_r2  [PP * CC];

// ---------------- primitives ---------------------------------------------------
__device__ __forceinline__ uint32_t smem_u32(const void* p) {
    uint32_t a;
    asm("{ .reg .u64 t; cvta.to.shared.u64 t, %1; cvt.u32.u64 %0, t; }"
        : "=r"(a) : "l"(p));
    return a;
}
__device__ __forceinline__ void ldsm4(uint32_t* r, uint32_t addr) {
    asm volatile("ldmatrix.sync.aligned.m8n8.x4.shared.b16 {%0,%1,%2,%3}, [%4];"
                 : "=r"(r[0]), "=r"(r[1]), "=r"(r[2]), "=r"(r[3]) : "r"(addr));
}
__device__ __forceinline__ void mma_f16(float* d, const uint32_t* a, const uint32_t* b) {
    asm volatile("mma.sync.aligned.m16n8k16.row.col.f32.f16.f16.f32 "
                 "{%0,%1,%2,%3}, {%4,%5,%6,%7}, {%8,%9}, {%0,%1,%2,%3};"
                 : "+f"(d[0]), "+f"(d[1]), "+f"(d[2]), "+f"(d[3])
                 : "r"(a[0]), "r"(a[1]), "r"(a[2]), "r"(a[3]), "r"(b[0]), "r"(b[1]));
}
__device__ __forceinline__ void cp16(uint32_t s, const void* g) {
    asm volatile("cp.async.cg.shared.global [%0], [%1], 16;" :: "r"(s), "l"(g) : "memory");
}
__device__ __forceinline__ void cp_commit() {
    asm volatile("cp.async.commit_group;" ::: "memory");
}
template<int N> __device__ __forceinline__ void cp_wait() {
    asm volatile("cp.async.wait_group %0;" :: "n"(N) : "memory");
}

// smem: stage = A(8K) + B(8K) = 16K; 3-stage pipeline = 48K
#define STG_BYTES   16384
#define DSMEM_BYTES 49152
// LN kernels: per-sample slab with stride-513 padding: 48 * 513 * 4 = 98496 B
#define LN_STRIDE   513
#define LN_SMEM     (HW * LN_STRIDE * 4)

// ---------------- tensor-core GEMM, 3-stage cp.async pipeline -----------------
// C[m,n] = A[m,:]·B[n,:], pure fp16 operands.
// Tile 64x64, BK=64, 128 threads (4 warps, 2x2 grid, 32x32 per warp).
template<bool BIAS, bool RELU, bool ADD, bool EMITF, bool EMITS>
__device__ __forceinline__ void tgemm_body(
    const __half* __restrict__ Ah, const __half* __restrict__ Bh,
    const float* __restrict__ bias, const float* __restrict__ addsrc,
    float* __restrict__ outf, __half* __restrict__ oh,
    int Nc, int K, int m0, int n0, uint8_t* dsm)
{
    const int tid  = threadIdx.x;
    const int lane = tid & 31, wid = tid >> 5;
    const int wm = wid & 1, wn = wid >> 1;       // 2x2 warp grid
    const uint32_t sbase = smem_u32(dsm);

    const int rA  = (lane & 7) + ((lane >> 3) & 1) * 8;
    const int kgA = (lane >> 4) & 1;
    const int rB  = (lane & 7) + ((lane >> 4) & 1) * 8;
    const int kgB = (lane >> 3) & 1;
    const int l7  = lane & 7;

    float acc[2][4][4];                          // 32x32 per warp
    #pragma unroll
    for (int mf = 0; mf < 2; mf++)
        #pragma unroll
        for (int nf = 0; nf < 4; nf++)
            #pragma unroll
            for (int q = 0; q < 4; q++) acc[mf][nf][q] = 0.f;

    const int nch = K >> 6;   // >= 4 for all our GEMMs

    auto stage = [&](int ch, int slot) {
        const int k0 = ch << 6;
        const uint32_t abase = sbase + slot * STG_BYTES;
        #pragma unroll
        for (int i = 0; i < 4; i++) {            // A: 64 rows x 8 groups
            int t = tid + i * 128;               // 0..511
            int r = t >> 3, g = t & 7;
            cp16(abase + r * 128 + ((g ^ (r & 7)) << 4),
                 Ah + (size_t)(m0 + r) * K + k0 + g * 8);
        }
        {                                        // B: 64 rows x 8 groups
            uint32_t dst = abase + 8192;
            #pragma unroll
            for (int i = 0; i < 4; i++) {
                int t = tid + i * 128;           // 0..511
                int r = t >> 3, g = t & 7;
                cp16(dst + r * 128 + ((g ^ (r & 7)) << 4),
                     Bh + (size_t)(n0 + r) * K + k0 + g * 8);
            }
        }
        cp_commit();
    };

    stage(0, 0); stage(1, 1);                    // prologue: 2 chunks in flight
    for (int ch = 0; ch < nch; ch++) {
        cp_wait<1>();                            // chunk ch landed
        __syncthreads();                         // all warps done with slot (ch-1)%3
        const int slot = ch % 3;
        const uint32_t sAu = sbase + slot * STG_BYTES;
        const uint32_t sBu = sAu + 8192;
        #pragma unroll
        for (int ks = 0; ks < 4; ks++) {
            uint32_t a[2][4], b[2][4];
            const int xA = ((ks * 2 + kgA) ^ l7) << 4;
            const int xB = ((ks * 2 + kgB) ^ l7) << 4;
            #pragma unroll
            for (int mf = 0; mf < 2; mf++) {
                int row = wm * 32 + mf * 16 + rA;
                ldsm4(a[mf], sAu + row * 128 + xA);
            }
            #pragma unroll
            for (int np = 0; np < 2; np++) {
                int row = wn * 32 + np * 16 + rB;
                ldsm4(b[np], sBu + row * 128 + xB);
            }
            #pragma unroll
            for (int mf = 0; mf < 2; mf++)
                #pragma unroll
                for (int nf = 0; nf < 4; nf++) {
                    int np = nf >> 1, sub = (nf & 1) << 1;
                    mma_f16(acc[mf][nf], a[mf], &b[np][sub]);
                }
        }
        if (ch + 2 < nch) stage(ch + 2, (ch + 2) % 3);
        else              cp_commit();           // keep one group per iter
    }
    // ---- epilogue ----
    const int mrow0 = m0 + wm * 32 + (lane >> 2);
    const int col0  = n0 + wn * 32 + (lane & 3) * 2;
    #pragma unroll
    for (int mf = 0; mf < 2; mf++)
        #pragma unroll
        for (int nf = 0; nf < 4; nf++)
            #pragma unroll
            for (int hf = 0; hf < 2; hf++) {
                int row = mrow0 + mf * 16 + hf * 8;
                int col = col0 + nf * 8;
                float vx = acc[mf][nf][hf * 2];
                float vy = acc[mf][nf][hf * 2 + 1];
                if (BIAS) { vx += bias[col]; vy += bias[col + 1]; }
                if (RELU) { vx = fmaxf(vx, 0.f); vy = fmaxf(vy, 0.f); }
                if (ADD) {
                    const float2 a2 = *(const float2*)&addsrc[(size_t)row * Nc + col];
                    vx += a2.x; vy += a2.y;
                }
                if (EMITF) *(float2*)&outf[(size_t)row * Nc + col] = make_float2(vx, vy);
                if (EMITS)
                    *(__half2*)&oh[(size_t)row * Nc + col] =
                        __halves2half2(__float2half_rn(vx), __float2half_rn(vy));
            }
}

template<bool BIAS, bool RELU, bool ADD, bool EMITF, bool EMITS>
__global__ __launch_bounds__(128) void tgemm_kernel(
    const __half* __restrict__ Ah, const __half* __restrict__ Bh,
    const float* __restrict__ bias, const float* __restrict__ addsrc,
    float* __restrict__ outf, __half* __restrict__ oh,
    int Nc, int K)
{
    extern __shared__ uint8_t dsm[];
    tgemm_body<BIAS, RELU, ADD, EMITF, EMITS>(Ah, Bh, bias, addsrc,
        outf, oh, Nc, K, blockIdx.y * 64, blockIdx.x * 64, dsm);
}

// dual projection: z=0 -> theta, z=1 -> phi (both fp16 out)
__global__ __launch_bounds__(128) void tgemm_dual_kernel(
    const __half* __restrict__ Ah,
    const __half* __restrict__ B0h, const __half* __restrict__ B1h,
    const float* __restrict__ bias0, const float* __restrict__ bias1,
    __half* __restrict__ thh, __half* __restrict__ phih, int Nc, int K)
{
    extern __shared__ uint8_t dsm[];
    bool z = blockIdx.z != 0;
    tgemm_body<true, false, false, false, true>(Ah, z ? B1h : B0h,
        z ? bias1 : bias0, nullptr, nullptr, z ? phih : thh,
        Nc, K, blockIdx.y * 64, blockIdx.x * 64, dsm);
}

// ---------------- prep: transpose+cast x AND cast all weights -----------------
__global__ __launch_bounds__(256) void prep_kernel(const float* __restrict__ x,
                                                   __half* __restrict__ xh,
                                                   const float* __restrict__ w0,
                                                   const float* __restrict__ w1,
                                                   const float* __restrict__ w2,
                                                   const float* __restrict__ w3,
                                                   __half* __restrict__ wh) {
    int tid = threadIdx.x;
    if (blockIdx.x < 256) {
        int j  = blockIdx.x >> 2;
        int c0 = (blockIdx.x & 3) * 128;
        __shared__ float t[128][49];
        const float* xb = x + j * (CC * HW);
        for (int idx = tid; idx < 128 * HW; idx += 256) {
            int cc = idx / HW, s = idx % HW;
            t[cc][s] = xb[(c0 + cc) * HW + s];
        }
        __syncthreads();
        size_t ob = (size_t)j * HW * CC;
        for (int idx = tid; idx < HW * 128; idx += 256) {
            int s = idx >> 7, cc = idx & 127;
            xh[ob + s * CC + c0 + cc] = __float2half_rn(t[cc][s]);
        }
    } else {
        int i = (blockIdx.x - 256) * 256 + tid;   // < 2*W1SZ + 2*W2SZ
        const float* src; int off;
        if (i < W1SZ)                  { src = w0; off = i; }
        else if (i < 2 * W1SZ)         { src = w1; off = i - W1SZ; }
        else if (i < 2 * W1SZ + W2SZ)  { src = w2; off = i - 2 * W1SZ; }
        else                           { src = w3; off = i - 2 * W1SZ - W2SZ; }
        wh[i] = __float2half_rn(src[off]);
    }
}

// ---------------- maxpool 2x2 on phi (fp16 in/out) ----------------------------
__global__ __launch_bounds__(256) void pool_kernel(const __half* __restrict__ phi,
                                                   __half* __restrict__ ph) {
    int m = blockIdx.x, i = blockIdx.y;
    int c = threadIdx.x;   // 256 = CI
    int phh = m >> 1, pw = m & 1;
    int s0 = (2 * phh) * WW + 2 * pw;
    const __half* b = phi + (size_t)(i * HW) * CI_ + c;
    float v = __half2float(b[(size_t)s0 * CI_]);
    v = fmaxf(v, __half2float(b[(size_t)(s0 + 1) * CI_]));
    v = fmaxf(v, __half2float(b[(size_t)(s0 + WW) * CI_]));
    v = fmaxf(v, __half2float(b[(size_t)(s0 + WW + 1) * CI_]));
    ph[(size_t)(i * NM + m) * CI_ + c] = __float2half_rn(v);
}

// ---------------- reduce F(half) -> M -----------------------------------------
__global__ __launch_bounds__(256) void reduceM_kernel(const __half* __restrict__ F,
                                                      float* __restrict__ Mv) {
    int p = blockIdx.x * 8 + (threadIdx.x >> 5);
    int lane = threadIdx.x & 31;
    const __half* row = F + (size_t)p * NCF;
    float s = 0.f;
    #pragma unroll
    for (int g = lane; g < NB; g += 32) {
        const uint2* q = (const uint2*)(row + 12 * g);
        uint2 u0 = q[0], u1 = q[1], u2 = q[2];
        __half2 h0 = *(__half2*)&u0.x, h1 = *(__half2*)&u0.y;
        __half2 h2 = *(__half2*)&u1.x, h3 = *(__half2*)&u1.y;
        __half2 h4 = *(__half2*)&u2.x, h5 = *(__half2*)&u2.y;
        __half2 m2 = __hmax2(__hmax2(h0, h1), __hmax2(__hmax2(h2, h3), __hmax2(h4, h5)));
        s += fmaxf(__half2float(__low2half(m2)), __half2float(__high2half(m2)));
    }
    #pragma unroll
    for (int o = 16; o > 0; o >>= 1) s += __shfl_down_sync(0xffffffffu, s, o);
    if (lane == 0) Mv[p] = s * (1.0f / 12.0f);
}

// ---------------- block reduction (16 warps) ----------------------------------
__device__ __forceinline__ float blockReduceSum512(float v, float* sbuf) {
    #pragma unroll
    for (int o = 16; o > 0; o >>= 1) v += __shfl_down_sync(0xffffffffu, v, o);
    int lane = threadIdx.x & 31, w = threadIdx.x >> 5;
    if (lane == 0) sbuf[w] = v;
    __syncthreads();
    v = (threadIdx.x < 16) ? sbuf[threadIdx.x] : 0.f;
    if (w == 0) {
        #pragma unroll
        for (int o = 8; o > 0; o >>= 1) v += __shfl_down_sync(0xffffffffu, v, o);
    }
    return v;
}

// ---------------- res1 + LN1: reads x (NCHW), emits f32 + fp16 ([s][c]) -------
__global__ __launch_bounds__(512) void ln1_kernel(const float* __restrict__ x,
                                                  const float* __restrict__ Mv,
                                                  const float* __restrict__ gam,
                                                  const float* __restrict__ bet,
                                                  float* __restrict__ xln,
                                                  __half* __restrict__ xh) {
    extern __shared__ float slab[];   // [HW][LN_STRIDE]  (spatial-major)
    int j = blockIdx.x, tid = threadIdx.x;
    __shared__ float sbuf[16];
    __shared__ float s_mu, s_rstd;
    __shared__ float s_scale[HW];
    if (tid < HW) s_scale[tid] = 1.0f + Mv[j * HW + tid];
    __syncthreads();
    const float* base = x + (size_t)j * (HW * CC);   // NCHW: idx = c*48+sp
    float sum = 0.f, sq = 0.f;
    for (int idx = tid; idx < HW * CC; idx += 512) {
        int c = idx / HW, sp = idx % HW;
        float v = base[idx] * s_scale[sp];
        slab[sp * LN_STRIDE + c] = v;
        sum += v; sq += v * v;
    }
    float ts = blockReduceSum512(sum, sbuf);
    __syncthreads();
    float tq = blockReduceSum512(sq, sbuf);
    if (tid == 0) {
        float mu = ts * (1.0f / (HW * CC));
        float var = tq * (1.0f / (HW * CC)) - mu * mu;
        s_mu = mu; s_rstd = rsqrtf(var + EPS_);
    }
    __syncthreads();
    float mu = s_mu, rstd = s_rstd;
    size_t ob = (size_t)j * (HW * CC);
    // output layout [s][c] (pixel-major, GEMM A layout)
    for (int idx = tid; idx < HW * CC; idx += 512) {
        int s = idx >> 9, c = idx & 511;
        float v = slab[s * LN_STRIDE + c];
        float r = (v - mu) * rstd * gam[c * HW + s] + bet[c * HW + s];
        xln[ob + idx] = r;
        xh[ob + idx] = __float2half_rn(r);
    }
}

// ---------------- LN2 + NCHW output (smem-cached sample) ----------------------
__global__ __launch_bounds__(512) void ln2_kernel(const float* __restrict__ r2,
                                                  const float* __restrict__ gam,
                                                  const float* __restrict__ bet,
                                                  float* __restrict__ out) {
    extern __shared__ float slab[];   // [HW][LN_STRIDE]
    int j = blockIdx.x, tid = threadIdx.x;
    __shared__ float sbuf[16];
    __shared__ float s_mu, s_rstd;
    const float* base = r2 + (size_t)j * (HW * CC);  // [s][c]
    float sum = 0.f, sq = 0.f;
    for (int idx = tid; idx < HW * CC; idx += 512) {
        int s = idx >> 9, c = idx & 511;
        float v = base[idx];
        slab[s * LN_STRIDE + c] = v;
        sum += v; sq += v * v;
    }
    float ts = blockReduceSum512(sum, sbuf);
    __syncthreads();
    float tq = blockReduceSum512(sq, sbuf);
    if (tid == 0) {
        float mu = ts * (1.0f / (HW * CC));
        float var = tq * (1.0f / (HW * CC)) - mu * mu;
        s_mu = mu; s_rstd = rsqrtf(var + EPS_);
    }
    __syncthreads();
    float mu = s_mu, rstd = s_rstd;
    float* o = out + (size_t)j * (HW * CC);
    // output idx = c*48 + sp (NCHW), smem read sp*513+c bank-safe
    for (int idx = tid; idx < HW * CC; idx += 512) {
        int c = idx / HW, sp = idx % HW;
        float v = slab[sp * LN_STRIDE + c];
        o[idx] = (v - mu) * rstd * gam[idx] + bet[idx];
    }
}

// ---------------- launcher ----------------------------------------------------
extern "C" void kernel_launch(void* const* d_in, const int* in_sizes, int n_in,
                              void* d_out, int out_size) {
    const float* x       = (const float*)d_in[0];
    const float* theta_w = (const float*)d_in[1];
    const float* theta_b = (const float*)d_in[2];
    const float* phi_w   = (const float*)d_in[3];
    const float* phi_b   = (const float*)d_in[4];
    const float* conv1_w = (const float*)d_in[5];
    const float* conv2_w = (const float*)d_in[6];
    const float* ln1_g   = (const float*)d_in[7];
    const float* ln1_b   = (const float*)d_in[8];
    const float* ln2_g   = (const float*)d_in[9];
    const float* ln2_b   = (const float*)d_in[10];
    float* out = (float*)d_out;

    float *Mv, *xln, *r2;
    __half *xth, *wh, *thh, *phih, *pph, *Fh, *xlnh, *y1h;
    cudaGetSymbolAddress((void**)&xth,  g_xth);
    cudaGetSymbolAddress((void**)&wh,   g_wh);
    cudaGetSymbolAddress((void**)&thh,  g_thh);
    cudaGetSymbolAddress((void**)&phih, g_phih);
    cudaGetSymbolAddress((void**)&pph,  g_pph);
    cudaGetSymbolAddress((void**)&Fh,   g_Fh);
    cudaGetSymbolAddress((void**)&Mv,   g_M);
    cudaGetSymbolAddress((void**)&xln,  g_xln);
    cudaGetSymbolAddress((void**)&xlnh, g_xlnh);
    cudaGetSymbolAddress((void**)&y1h,  g_y1h);
    cudaGetSymbolAddress((void**)&r2,   g_r2);

    cudaFuncSetAttribute(tgemm_dual_kernel,
        cudaFuncAttributeMaxDynamicSharedMemorySize, DSMEM_BYTES);
    cudaFuncSetAttribute(tgemm_kernel<false, false, false, false, true>,
        cudaFuncAttributeMaxDynamicSharedMemorySize, DSMEM_BYTES);
    cudaFuncSetAttribute(tgemm_kernel<false, true, false, false, true>,
        cudaFuncAttributeMaxDynamicSharedMemorySize, DSMEM_BYTES);
    cudaFuncSetAttribute(tgemm_kernel<false, false, true, true, false>,
        cudaFuncAttributeMaxDynamicSharedMemorySize, DSMEM_BYTES);
    cudaFuncSetAttribute(ln1_kernel,
        cudaFuncAttributeMaxDynamicSharedMemorySize, LN_SMEM);
    cudaFuncSetAttribute(ln2_kernel,
        cudaFuncAttributeMaxDynamicSharedMemorySize, LN_SMEM);

    const int W1 = W1SZ, W2 = W2SZ;
    const int SPLIT_BLOCKS = (2 * W1 + 2 * W2) / 256;   // 3072

    // transpose+cast x + cast all weights in one launch
    prep_kernel<<<256 + SPLIT_BLOCKS, 256>>>(x, xth,
        theta_w, phi_w, conv1_w, conv2_w, wh);

    // theta & phi (both fp16 out): [3072,512]@[256,512]^T
    tgemm_dual_kernel<<<dim3(CI_ / 64, PP / 64, 2), 128, DSMEM_BYTES>>>(
        xth, wh, wh + W1, theta_b, phi_b, thh, phih, CI_, CC);
    pool_kernel<<<dim3(NM, NB), 256>>>(phih, pph);
    // F = theta @ phip^T (fp16 out): [3072,256]@[768,256]^T
    tgemm_kernel<false, false, false, false, true><<<dim3(NCF / 64, PP / 64), 128, DSMEM_BYTES>>>(
        thh, pph, nullptr, nullptr, nullptr, Fh, NCF, CI_);
    reduceM_kernel<<<PP / 8, 256>>>(Fh, Mv);
    ln1_kernel<<<NB, 512, LN_SMEM>>>(x, Mv, ln1_g, ln1_b, xln, xlnh);
    // y1 = relu(xln @ conv1_w^T) -> half
    tgemm_kernel<false, true, false, false, true><<<dim3(CC / 64, PP / 64), 128, DSMEM_BYTES>>>(
        xlnh, wh + 2 * W1, nullptr, nullptr, nullptr, y1h, CC, CC);
    // r2 = xln + y1 @ conv2_w^T -> f32
    tgemm_kernel<false, false, true, true, false><<<dim3(CC / 64, PP / 64), 128, DSMEM_BYTES>>>(
        y1h, wh + 2 * W1 + W2, nullptr, xln, r2, nullptr, CC, CC);
    ln2_kernel<<<NB, 512, LN_SMEM>>>(r2, ln2_g, ln2_b, out);
}

// round 17
// speedup vs baseline: 1.8624x; 1.0537x over previous
#include <cuda_runtime.h>
#include <cuda_fp16.h>
#include <cstdint>
#include <math.h>

// Problem constants
#define NB   64
#define CC   512
#define CI_  256
#define HH   12
#define WW   4
#define HW   48
#define PP   (NB*HW)     // 3072
#define NM   12
#define NCF  (NB*NM)     // 768
#define EPS_ 1e-5f
#define W1SZ (CI_*CC)    // 131072
#define W2SZ (CC*CC)     // 262144

// ---------------- scratch (device globals) ------------------------------------
__device__ __half  g_xth [PP * CC];
__device__ __half  g_wh  [2 * W1SZ + 2 * W2SZ];   // fp16 weights (B role)
__device__ __half  g_thh [PP * CI_];
__device__ __half  g_phih[PP * CI_];
__device__ __half  g_pph [NCF * CI_];
__device__ __half  g_Fh  [PP * NCF];
__device__ float   g_M   [PP];
__device__ __half  g_xlnh[PP * CC];
__device__ __half  g_y1h [PP * CC];
__device__ __half  g_r2h [PP * CC];

// ---------------- primitives ---------------------------------------------------
__device__ __forceinline__ uint32_t smem_u32(const void* p) {
    uint32_t a;
    asm("{ .reg .u64 t; cvta.to.shared.u64 t, %1; cvt.u32.u64 %0, t; }"
        : "=r"(a) : "l"(p));
    return a;
}
__device__ __forceinline__ void ldsm4(uint32_t* r, uint32_t addr) {
    asm volatile("ldmatrix.sync.aligned.m8n8.x4.shared.b16 {%0,%1,%2,%3}, [%4];"
                 : "=r"(r[0]), "=r"(r[1]), "=r"(r[2]), "=r"(r[3]) : "r"(addr));
}
__device__ __forceinline__ void mma_f16(float* d, const uint32_t* a, const uint32_t* b) {
    asm volatile("mma.sync.aligned.m16n8k16.row.col.f32.f16.f16.f32 "
                 "{%0,%1,%2,%3}, {%4,%5,%6,%7}, {%8,%9}, {%0,%1,%2,%3};"
                 : "+f"(d[0]), "+f"(d[1]), "+f"(d[2]), "+f"(d[3])
                 : "r"(a[0]), "r"(a[1]), "r"(a[2]), "r"(a[3]), "r"(b[0]), "r"(b[1]));
}
__device__ __forceinline__ void cp16(uint32_t s, const void* g) {
    asm volatile("cp.async.cg.shared.global [%0], [%1], 16;" :: "r"(s), "l"(g) : "memory");
}
__device__ __forceinline__ void cp_commit() {
    asm volatile("cp.async.commit_group;" ::: "memory");
}
template<int N> __device__ __forceinline__ void cp_wait() {
    asm volatile("cp.async.wait_group %0;" :: "n"(N) : "memory");
}

// smem: stage = A(8K) + B(8K) = 16K; 3-stage pipeline = 48K
#define STG_BYTES   16384
#define DSMEM_BYTES 49152
// LN kernels: per-sample slab with stride-513 padding: 48 * 513 * 4 = 98496 B
#define LN_STRIDE   513
#define LN_SMEM     (HW * LN_STRIDE * 4)

// ---------------- tensor-core GEMM, 3-stage cp.async pipeline -----------------
// C[m,n] = A[m,:]·B[n,:], pure fp16 operands.
// Tile 64x64, BK=64, 128 threads (4 warps, 2x2 grid, 32x32 per warp).
// ADD reads fp16 addsrc; EMITS writes fp16, EMITF writes fp32.
template<bool BIAS, bool RELU, bool ADD, bool EMITF, bool EMITS>
__device__ __forceinline__ void tgemm_body(
    const __half* __restrict__ Ah, const __half* __restrict__ Bh,
    const float* __restrict__ bias, const __half* __restrict__ addsrc,
    float* __restrict__ outf, __half* __restrict__ oh,
    int Nc, int K, int m0, int n0, uint8_t* dsm)
{
    const int tid  = threadIdx.x;
    const int lane = tid & 31, wid = tid >> 5;
    const int wm = wid & 1, wn = wid >> 1;       // 2x2 warp grid
    const uint32_t sbase = smem_u32(dsm);

    const int rA  = (lane & 7) + ((lane >> 3) & 1) * 8;
    const int kgA = (lane >> 4) & 1;
    const int rB  = (lane & 7) + ((lane >> 4) & 1) * 8;
    const int kgB = (lane >> 3) & 1;
    const int l7  = lane & 7;

    float acc[2][4][4];                          // 32x32 per warp
    #pragma unroll
    for (int mf = 0; mf < 2; mf++)
        #pragma unroll
        for (int nf = 0; nf < 4; nf++)
            #pragma unroll
            for (int q = 0; q < 4; q++) acc[mf][nf][q] = 0.f;

    const int nch = K >> 6;   // >= 4 for all our GEMMs

    auto stage = [&](int ch, int slot) {
        const int k0 = ch << 6;
        const uint32_t abase = sbase + slot * STG_BYTES;
        #pragma unroll
        for (int i = 0; i < 4; i++) {            // A: 64 rows x 8 groups
            int t = tid + i * 128;               // 0..511
            int r = t >> 3, g = t & 7;
            cp16(abase + r * 128 + ((g ^ (r & 7)) << 4),
                 Ah + (size_t)(m0 + r) * K + k0 + g * 8);
        }
        {                                        // B: 64 rows x 8 groups
            uint32_t dst = abase + 8192;
            #pragma unroll
            for (int i = 0; i < 4; i++) {
                int t = tid + i * 128;           // 0..511
                int r = t >> 3, g = t & 7;
                cp16(dst + r * 128 + ((g ^ (r & 7)) << 4),
                     Bh + (size_t)(n0 + r) * K + k0 + g * 8);
            }
        }
        cp_commit();
    };

    stage(0, 0); stage(1, 1);                    // prologue: 2 chunks in flight
    for (int ch = 0; ch < nch; ch++) {
        cp_wait<1>();                            // chunk ch landed
        __syncthreads();                         // all warps done with slot (ch-1)%3
        const int slot = ch % 3;
        const uint32_t sAu = sbase + slot * STG_BYTES;
        const uint32_t sBu = sAu + 8192;
        #pragma unroll
        for (int ks = 0; ks < 4; ks++) {
            uint32_t a[2][4], b[2][4];
            const int xA = ((ks * 2 + kgA) ^ l7) << 4;
            const int xB = ((ks * 2 + kgB) ^ l7) << 4;
            #pragma unroll
            for (int mf = 0; mf < 2; mf++) {
                int row = wm * 32 + mf * 16 + rA;
                ldsm4(a[mf], sAu + row * 128 + xA);
            }
            #pragma unroll
            for (int np = 0; np < 2; np++) {
                int row = wn * 32 + np * 16 + rB;
                ldsm4(b[np], sBu + row * 128 + xB);
            }
            #pragma unroll
            for (int mf = 0; mf < 2; mf++)
                #pragma unroll
                for (int nf = 0; nf < 4; nf++) {
                    int np = nf >> 1, sub = (nf & 1) << 1;
                    mma_f16(acc[mf][nf], a[mf], &b[np][sub]);
                }
        }
        if (ch + 2 < nch) stage(ch + 2, (ch + 2) % 3);
        else              cp_commit();           // keep one group per iter
    }
    // ---- epilogue ----
    const int mrow0 = m0 + wm * 32 + (lane >> 2);
    const int col0  = n0 + wn * 32 + (lane & 3) * 2;
    #pragma unroll
    for (int mf = 0; mf < 2; mf++)
        #pragma unroll
        for (int nf = 0; nf < 4; nf++)
            #pragma unroll
            for (int hf = 0; hf < 2; hf++) {
                int row = mrow0 + mf * 16 + hf * 8;
                int col = col0 + nf * 8;
                float vx = acc[mf][nf][hf * 2];
                float vy = acc[mf][nf][hf * 2 + 1];
                if (BIAS) { vx += bias[col]; vy += bias[col + 1]; }
                if (RELU) { vx = fmaxf(vx, 0.f); vy = fmaxf(vy, 0.f); }
                if (ADD) {
                    __half2 a2 = *(const __half2*)&addsrc[(size_t)row * Nc + col];
                    vx += __half2float(__low2half(a2));
                    vy += __half2float(__high2half(a2));
                }
                if (EMITF) *(float2*)&outf[(size_t)row * Nc + col] = make_float2(vx, vy);
                if (EMITS)
                    *(__half2*)&oh[(size_t)row * Nc + col] =
                        __halves2half2(__float2half_rn(vx), __float2half_rn(vy));
            }
}

template<bool BIAS, bool RELU, bool ADD, bool EMITF, bool EMITS>
__global__ __launch_bounds__(128) void tgemm_kernel(
    const __half* __restrict__ Ah, const __half* __restrict__ Bh,
    const float* __restrict__ bias, const __half* __restrict__ addsrc,
    float* __restrict__ outf, __half* __restrict__ oh,
    int Nc, int K)
{
    extern __shared__ uint8_t dsm[];
    tgemm_body<BIAS, RELU, ADD, EMITF, EMITS>(Ah, Bh, bias, addsrc,
        outf, oh, Nc, K, blockIdx.y * 64, blockIdx.x * 64, dsm);
}

// dual projection: z=0 -> theta, z=1 -> phi (both fp16 out)
__global__ __launch_bounds__(128) void tgemm_dual_kernel(
    const __half* __restrict__ Ah,
    const __half* __restrict__ B0h, const __half* __restrict__ B1h,
    const float* __restrict__ bias0, const float* __restrict__ bias1,
    __half* __restrict__ thh, __half* __restrict__ phih, int Nc, int K)
{
    extern __shared__ uint8_t dsm[];
    bool z = blockIdx.z != 0;
    tgemm_body<true, false, false, false, true>(Ah, z ? B1h : B0h,
        z ? bias1 : bias0, nullptr, nullptr, z ? phih : thh,
        Nc, K, blockIdx.y * 64, blockIdx.x * 64, dsm);
}

// ---------------- prep: transpose+cast x AND cast all weights -----------------
__global__ __launch_bounds__(256) void prep_kernel(const float* __restrict__ x,
                                                   __half* __restrict__ xh,
                                                   const float* __restrict__ w0,
                                                   const float* __restrict__ w1,
                                                   const float* __restrict__ w2,
                                                   const float* __restrict__ w3,
                                                   __half* __restrict__ wh) {
    int tid = threadIdx.x;
    if (blockIdx.x < 256) {
        int j  = blockIdx.x >> 2;
        int c0 = (blockIdx.x & 3) * 128;
        __shared__ float t[128][49];
        const float* xb = x + j * (CC * HW);
        for (int idx = tid; idx < 128 * HW; idx += 256) {
            int cc = idx / HW, s = idx % HW;
            t[cc][s] = xb[(c0 + cc) * HW + s];
        }
        __syncthreads();
        size_t ob = (size_t)j * HW * CC;
        for (int idx = tid; idx < HW * 128; idx += 256) {
            int s = idx >> 7, cc = idx & 127;
            xh[ob + s * CC + c0 + cc] = __float2half_rn(t[cc][s]);
        }
    } else {
        int i = (blockIdx.x - 256) * 256 + tid;   // < 2*W1SZ + 2*W2SZ
        const float* src; int off;
        if (i < W1SZ)                  { src = w0; off = i; }
        else if (i < 2 * W1SZ)         { src = w1; off = i - W1SZ; }
        else if (i < 2 * W1SZ + W2SZ)  { src = w2; off = i - 2 * W1SZ; }
        else                           { src = w3; off = i - 2 * W1SZ - W2SZ; }
        wh[i] = __float2half_rn(src[off]);
    }
}

// ---------------- maxpool 2x2 on phi (fp16 in/out) ----------------------------
__global__ __launch_bounds__(256) void pool_kernel(const __half* __restrict__ phi,
                                                   __half* __restrict__ ph) {
    int m = blockIdx.x, i = blockIdx.y;
    int c = threadIdx.x;   // 256 = CI
    int phh = m >> 1, pw = m & 1;
    int s0 = (2 * phh) * WW + 2 * pw;
    const __half* b = phi + (size_t)(i * HW) * CI_ + c;
    float v = __half2float(b[(size_t)s0 * CI_]);
    v = fmaxf(v, __half2float(b[(size_t)(s0 + 1) * CI_]));
    v = fmaxf(v, __half2float(b[(size_t)(s0 + WW) * CI_]));
    v = fmaxf(v, __half2float(b[(size_t)(s0 + WW + 1) * CI_]));
    ph[(size_t)(i * NM + m) * CI_ + c] = __float2half_rn(v);
}

// ---------------- reduce F(half) -> M -----------------------------------------
__global__ __launch_bounds__(256) void reduceM_kernel(const __half* __restrict__ F,
                                                      float* __restrict__ Mv) {
    int p = blockIdx.x * 8 + (threadIdx.x >> 5);
    int lane = threadIdx.x & 31;
    const __half* row = F + (size_t)p * NCF;
    float s = 0.f;
    #pragma unroll
    for (int g = lane; g < NB; g += 32) {
        const uint2* q = (const uint2*)(row + 12 * g);
        uint2 u0 = q[0], u1 = q[1], u2 = q[2];
        __half2 h0 = *(__half2*)&u0.x, h1 = *(__half2*)&u0.y;
        __half2 h2 = *(__half2*)&u1.x, h3 = *(__half2*)&u1.y;
        __half2 h4 = *(__half2*)&u2.x, h5 = *(__half2*)&u2.y;
        __half2 m2 = __hmax2(__hmax2(h0, h1), __hmax2(__hmax2(h2, h3), __hmax2(h4, h5)));
        s += fmaxf(__half2float(__low2half(m2)), __half2float(__high2half(m2)));
    }
    #pragma unroll
    for (int o = 16; o > 0; o >>= 1) s += __shfl_down_sync(0xffffffffu, s, o);
    if (lane == 0) Mv[p] = s * (1.0f / 12.0f);
}

// ---------------- block reduction (16 warps) ----------------------------------
__device__ __forceinline__ float blockReduceSum512(float v, float* sbuf) {
    #pragma unroll
    for (int o = 16; o > 0; o >>= 1) v += __shfl_down_sync(0xffffffffu, v, o);
    int lane = threadIdx.x & 31, w = threadIdx.x >> 5;
    if (lane == 0) sbuf[w] = v;
    __syncthreads();
    v = (threadIdx.x < 16) ? sbuf[threadIdx.x] : 0.f;
    if (w == 0) {
        #pragma unroll
        for (int o = 8; o > 0; o >>= 1) v += __shfl_down_sync(0xffffffffu, v, o);
    }
    return v;
}

// ---------------- res1 + LN1: reads x (NCHW), emits fp16 ([s][c]) -------------
__global__ __launch_bounds__(512) void ln1_kernel(const float* __restrict__ x,
                                                  const float* __restrict__ Mv,
                                                  const float* __restrict__ gam,
                                                  const float* __restrict__ bet,
                                                  __half* __restrict__ xh) {
    extern __shared__ float slab[];   // [HW][LN_STRIDE]  (spatial-major)
    int j = blockIdx.x, tid = threadIdx.x;
    __shared__ float sbuf[16];
    __shared__ float s_mu, s_rstd;
    __shared__ float s_scale[HW];
    if (tid < HW) s_scale[tid] = 1.0f + Mv[j * HW + tid];
    __syncthreads();
    const float* base = x + (size_t)j * (HW * CC);   // NCHW: idx = c*48+sp
    float sum = 0.f, sq = 0.f;
    for (int idx = tid; idx < HW * CC; idx += 512) {
        int c = idx / HW, sp = idx % HW;
        float v = base[idx] * s_scale[sp];
        slab[sp * LN_STRIDE + c] = v;
        sum += v; sq += v * v;
    }
    float ts = blockReduceSum512(sum, sbuf);
    __syncthreads();
    float tq = blockReduceSum512(sq, sbuf);
    if (tid == 0) {
        float mu = ts * (1.0f / (HW * CC));
        float var = tq * (1.0f / (HW * CC)) - mu * mu;
        s_mu = mu; s_rstd = rsqrtf(var + EPS_);
    }
    __syncthreads();
    float mu = s_mu, rstd = s_rstd;
    size_t ob = (size_t)j * (HW * CC);
    // output layout [s][c] (pixel-major, GEMM A layout)
    for (int idx = tid; idx < HW * CC; idx += 512) {
        int s = idx >> 9, c = idx & 511;
        float v = slab[s * LN_STRIDE + c];
        float r = (v - mu) * rstd * gam[c * HW + s] + bet[c * HW + s];
        xh[ob + idx] = __float2half_rn(r);
    }
}

// ---------------- LN2 (half input) + NCHW output ------------------------------
__global__ __launch_bounds__(512) void ln2_kernel(const __half* __restrict__ r2,
                                                  const float* __restrict__ gam,
                                                  const float* __restrict__ bet,
                                                  float* __restrict__ out) {
    extern __shared__ float slab[];   // [HW][LN_STRIDE]
    int j = blockIdx.x, tid = threadIdx.x;
    __shared__ float sbuf[16];
    __shared__ float s_mu, s_rstd;
    const __half* base = r2 + (size_t)j * (HW * CC);  // [s][c]
    float sum = 0.f, sq = 0.f;
    for (int idx = tid; idx < HW * CC; idx += 512) {
        int s = idx >> 9, c = idx & 511;
        float v = __half2float(base[idx]);
        slab[s * LN_STRIDE + c] = v;
        sum += v; sq += v * v;
    }
    float ts = blockReduceSum512(sum, sbuf);
    __syncthreads();
    float tq = blockReduceSum512(sq, sbuf);
    if (tid == 0) {
        float mu = ts * (1.0f / (HW * CC));
        float var = tq * (1.0f / (HW * CC)) - mu * mu;
        s_mu = mu; s_rstd = rsqrtf(var + EPS_);
    }
    __syncthreads();
    float mu = s_mu, rstd = s_rstd;
    float* o = out + (size_t)j * (HW * CC);
    // output idx = c*48 + sp (NCHW), smem read sp*513+c bank-safe
    for (int idx = tid; idx < HW * CC; idx += 512) {
        int c = idx / HW, sp = idx % HW;
        float v = slab[sp * LN_STRIDE + c];
        o[idx] = (v - mu) * rstd * gam[idx] + bet[idx];
    }
}

// ---------------- launcher ----------------------------------------------------
extern "C" void kernel_launch(void* const* d_in, const int* in_sizes, int n_in,
                              void* d_out, int out_size) {
    const float* x       = (const float*)d_in[0];
    const float* theta_w = (const float*)d_in[1];
    const float* theta_b = (const float*)d_in[2];
    const float* phi_w   = (const float*)d_in[3];
    const float* phi_b   = (const float*)d_in[4];
    const float* conv1_w = (const float*)d_in[5];
    const float* conv2_w = (const float*)d_in[6];
    const float* ln1_g   = (const float*)d_in[7];
    const float* ln1_b   = (const float*)d_in[8];
    const float* ln2_g   = (const float*)d_in[9];
    const float* ln2_b   = (const float*)d_in[10];
    float* out = (float*)d_out;

    float *Mv;
    __half *xth, *wh, *thh, *phih, *pph, *Fh, *xlnh, *y1h, *r2h;
    cudaGetSymbolAddress((void**)&xth,  g_xth);
    cudaGetSymbolAddress((void**)&wh,   g_wh);
    cudaGetSymbolAddress((void**)&thh,  g_thh);
    cudaGetSymbolAddress((void**)&phih, g_phih);
    cudaGetSymbolAddress((void**)&pph,  g_pph);
    cudaGetSymbolAddress((void**)&Fh,   g_Fh);
    cudaGetSymbolAddress((void**)&Mv,   g_M);
    cudaGetSymbolAddress((void**)&xlnh, g_xlnh);
    cudaGetSymbolAddress((void**)&y1h,  g_y1h);
    cudaGetSymbolAddress((void**)&r2h,  g_r2h);

    cudaFuncSetAttribute(tgemm_dual_kernel,
        cudaFuncAttributeMaxDynamicSharedMemorySize, DSMEM_BYTES);
    cudaFuncSetAttribute(tgemm_kernel<false, false, false, false, true>,
        cudaFuncAttributeMaxDynamicSharedMemorySize, DSMEM_BYTES);
    cudaFuncSetAttribute(tgemm_kernel<false, true, false, false, true>,
        cudaFuncAttributeMaxDynamicSharedMemorySize, DSMEM_BYTES);
    cudaFuncSetAttribute(tgemm_kernel<false, false, true, false, true>,
        cudaFuncAttributeMaxDynamicSharedMemorySize, DSMEM_BYTES);
    cudaFuncSetAttribute(ln1_kernel,
        cudaFuncAttributeMaxDynamicSharedMemorySize, LN_SMEM);
    cudaFuncSetAttribute(ln2_kernel,
        cudaFuncAttributeMaxDynamicSharedMemorySize, LN_SMEM);

    const int W1 = W1SZ, W2 = W2SZ;
    const int SPLIT_BLOCKS = (2 * W1 + 2 * W2) / 256;   // 3072

    // transpose+cast x + cast all weights in one launch
    prep_kernel<<<256 + SPLIT_BLOCKS, 256>>>(x, xth,
        theta_w, phi_w, conv1_w, conv2_w, wh);

    // theta & phi (both fp16 out): [3072,512]@[256,512]^T
    tgemm_dual_kernel<<<dim3(CI_ / 64, PP / 64, 2), 128, DSMEM_BYTES>>>(
        xth, wh, wh + W1, theta_b, phi_b, thh, phih, CI_, CC);
    pool_kernel<<<dim3(NM, NB), 256>>>(phih, pph);
    // F = theta @ phip^T (fp16 out): [3072,256]@[768,256]^T
    tgemm_kernel<false, false, false, false, true><<<dim3(NCF / 64, PP / 64), 128, DSMEM_BYTES>>>(
        thh, pph, nullptr, nullptr, nullptr, Fh, NCF, CI_);
    reduceM_kernel<<<PP / 8, 256>>>(Fh, Mv);
    ln1_kernel<<<NB, 512, LN_SMEM>>>(x, Mv, ln1_g, ln1_b, xlnh);
    // y1 = relu(xln @ conv1_w^T) -> half
    tgemm_kernel<false, true, false, false, true><<<dim3(CC / 64, PP / 64), 128, DSMEM_BYTES>>>(
        xlnh, wh + 2 * W1, nullptr, nullptr, nullptr, y1h, CC, CC);
    // r2 = xln + y1 @ conv2_w^T -> half
    tgemm_kernel<false, false, true, false, true><<<dim3(CC / 64, PP / 64), 128, DSMEM_BYTES>>>(
        y1h, wh + 2 * W1 + W2, nullptr, xlnh, nullptr, r2h, CC, CC);
    ln2_kernel<<<NB, 512, LN_SMEM>>>(r2h, ln2_g, ln2_b, out);
}